// round 6
// baseline (speedup 1.0000x reference)
#include <cuda_runtime.h>
#include <mma.h>

using namespace nvcuda;

#define TM       32          // nodes per CTA
#define VLD      132         // smem leading dim (floats)
#define NTHREADS 512         // 16 warps

// RNA tf32-rounded weights (original layouts), filled by prep_kernel.
__device__ float g_U[128 * 128];
__device__ float g_V[128 * 128];
__device__ float g_m1[256 * 128];
__device__ float g_m2[128 * 384];

__device__ __forceinline__ float ftf32(float x) {
    float y;
    asm("cvt.rna.tf32.f32 %0, %1;" : "=f"(y) : "f"(x));
    return y;
}

__global__ void prep_kernel(const float* __restrict__ Uw,
                            const float* __restrict__ Vw,
                            const float* __restrict__ m1w,
                            const float* __restrict__ m2w) {
    int i = blockIdx.x * blockDim.x + threadIdx.x;
    if (i < 16384) { g_U[i] = ftf32(Uw[i]); g_V[i] = ftf32(Vw[i]); }
    if (i < 32768) g_m1[i] = ftf32(m1w[i]);
    if (i < 49152) g_m2[i] = ftf32(m2w[i]);
}

using FragA = wmma::fragment<wmma::matrix_a, 16, 16, 8, wmma::precision::tf32, wmma::row_major>;
using FragB = wmma::fragment<wmma::matrix_b, 16, 16, 8, wmma::precision::tf32, wmma::row_major>;
using FragC = wmma::fragment<wmma::accumulator, 16, 16, 8, float>;

__global__ __launch_bounds__(NTHREADS, 1)
void painn_kernel(const float* __restrict__ node_feat,
                  const float* __restrict__ U_b,
                  const float* __restrict__ V_b,
                  const float* __restrict__ m1_b,
                  const float* __restrict__ m2_b,
                  float* __restrict__ out) {
    extern __shared__ float smem[];
    float* sUv    = smem;                  // [3][32][VLD] biased Uv (raw until fix pass)
    float* sOut   = sUv    + 3 * 32 * VLD; // [3][32][VLD] stage-4 out; first 32xVLD aliases sv
    float* sVn    = sOut   + 3 * 32 * VLD; // [32][VLD] vn2 raw -> vn (tf32)
    float* sInner = sVn    + 32 * VLD;     // [32][VLD] inner raw -> inner
    float* sH     = sInner + 32 * VLD;     // [32][VLD]; aliases su until stage 3
    float* sSu = sH;
    float* sSv = sOut;

    const int tid  = threadIdx.x;
    const int w    = tid >> 5;             // 0..15
    const size_t base = (size_t)blockIdx.x * (TM * 512);
    const float* nf = node_feat + base;
    float* op = out + base;

    // ---------- Stage 1: Uv/Vv GEMMs straight from global A ----------
    // warp (mt = w&1, nt = w>>1): 6 accumulators (U,V x c=0..2)
    {
        const int mt = w & 1;
        const int nt = w >> 1;
        FragC aU[3], aV[3];
        #pragma unroll
        for (int c = 0; c < 3; ++c) {
            wmma::fill_fragment(aU[c], 0.0f);
            wmma::fill_fragment(aV[c], 0.0f);
        }
        const float* Abase = nf + (size_t)(mt * 16) * 512 + 128;
        #pragma unroll
        for (int k = 0; k < 16; ++k) {
            FragB bU, bV;
            wmma::load_matrix_sync(bU, g_U + k * 8 * 128 + nt * 16, 128);
            wmma::load_matrix_sync(bV, g_V + k * 8 * 128 + nt * 16, 128);
            #pragma unroll
            for (int c = 0; c < 3; ++c) {
                FragA af;
                wmma::load_matrix_sync(af, Abase + c * 128 + k * 8, 512);
                wmma::mma_sync(aU[c], af, bU, aU[c]);
                wmma::mma_sync(aV[c], af, bV, aV[c]);
            }
        }
        // elementwise fragment combines (layout-agnostic)
        FragC fsu, fsv, finn, fvn2;
        #pragma unroll
        for (int i = 0; i < fsu.num_elements; ++i) {
            float u0 = aU[0].x[i], u1 = aU[1].x[i], u2 = aU[2].x[i];
            float v0 = aV[0].x[i], v1 = aV[1].x[i], v2 = aV[2].x[i];
            fsu.x[i]  = u0 + u1 + u2;
            fsv.x[i]  = v0 + v1 + v2;
            finn.x[i] = u0 * v0 + u1 * v1 + u2 * v2;
            fvn2.x[i] = v0 * v0 + v1 * v1 + v2 * v2;
        }
        float* toff = sUv + mt * 16 * VLD + nt * 16;
        #pragma unroll
        for (int c = 0; c < 3; ++c)
            wmma::store_matrix_sync(toff + c * 32 * VLD, aU[c], VLD, wmma::mem_row_major);
        wmma::store_matrix_sync(sInner + mt * 16 * VLD + nt * 16, finn, VLD, wmma::mem_row_major);
        wmma::store_matrix_sync(sVn    + mt * 16 * VLD + nt * 16, fvn2, VLD, wmma::mem_row_major);
        wmma::store_matrix_sync(sSu    + mt * 16 * VLD + nt * 16, fsu,  VLD, wmma::mem_row_major);
        wmma::store_matrix_sync(sSv    + mt * 16 * VLD + nt * 16, fsv,  VLD, wmma::mem_row_major);
    }
    __syncthreads();

    // ---------- bias fix: Uv += ub; inner/vn2 corrected analytically ----------
    for (int q = tid; q < TM * 128; q += NTHREADS) {
        int n = q >> 7, g = q & 127;
        float ub = U_b[g], vb = V_b[g];
        float su = sSu[n * VLD + g];
        float sv = sSv[n * VLD + g];
        sUv[0 * 32 * VLD + n * VLD + g] += ub;
        sUv[1 * 32 * VLD + n * VLD + g] += ub;
        sUv[2 * 32 * VLD + n * VLD + g] += ub;
        float inner = sInner[n * VLD + g] + ub * sv + vb * su + 3.0f * ub * vb;
        sInner[n * VLD + g] = inner;
        float vn2 = sVn[n * VLD + g] + 2.0f * vb * sv + 3.0f * vb * vb;
        sVn[n * VLD + g] = ftf32(sqrtf(fmaxf(vn2, 0.0f)));
    }
    __syncthreads();   // sSu(sH), sSv(sOut) now dead

    // ---------- Stage 3: h = silu([Vn | scal] @ m1 + b) ----------
    {
        const int mt = w & 1;
        const int nt = w >> 1;
        FragC acc0, acc1;
        wmma::fill_fragment(acc0, 0.0f);
        wmma::fill_fragment(acc1, 0.0f);
        const float* scalA = nf + (size_t)(mt * 16) * 512;
        #pragma unroll
        for (int k = 0; k < 16; ++k) {
            FragA a0, a1;
            FragB b0, b1;
            wmma::load_matrix_sync(a0, sVn + mt * 16 * VLD + k * 8, VLD);
            wmma::load_matrix_sync(b0, g_m1 + (k * 8) * 128 + nt * 16, 128);
            wmma::load_matrix_sync(a1, scalA + k * 8, 512);
            wmma::load_matrix_sync(b1, g_m1 + (128 + k * 8) * 128 + nt * 16, 128);
            wmma::mma_sync(acc0, a0, b0, acc0);
            wmma::mma_sync(acc1, a1, b1, acc1);
        }
        #pragma unroll
        for (int i = 0; i < acc0.num_elements; ++i)
            acc0.x[i] += acc1.x[i];
        wmma::store_matrix_sync(sH + mt * 16 * VLD + nt * 16, acc0, VLD, wmma::mem_row_major);
    }
    __syncthreads();

    // silu + round
    for (int q = tid; q < TM * 128; q += NTHREADS) {
        int n = q >> 7, g = q & 127;
        float x = sH[n * VLD + g] + m1_b[g];
        sH[n * VLD + g] = ftf32(x / (1.0f + __expf(-x)));
    }
    __syncthreads();

    // ---------- Stage 4: mlp_out = h @ m2 (48 tile-tasks, 3 per warp) ----------
    #pragma unroll
    for (int p = 0; p < 3; ++p) {
        int t = w * 3 + p;               // 0..47
        int nt_g = t >> 1;
        int mt = t & 1;
        FragC acc;
        wmma::fill_fragment(acc, 0.0f);
        #pragma unroll
        for (int k = 0; k < 16; ++k) {
            FragA a;
            FragB b;
            wmma::load_matrix_sync(a, sH + mt * 16 * VLD + k * 8, VLD);
            wmma::load_matrix_sync(b, g_m2 + k * 8 * 384 + nt_g * 16, 384);
            wmma::mma_sync(acc, a, b, acc);
        }
        int blk  = nt_g >> 3;
        int colc = (nt_g & 7) * 16;
        wmma::store_matrix_sync(sOut + blk * 32 * VLD + mt * 16 * VLD + colc,
                                acc, VLD, wmma::mem_row_major);
    }
    __syncthreads();

    // ---------- Epilogue: fp32 residual path ----------
    for (int q = tid; q < TM * 32; q += NTHREADS) {
        int n = q >> 5;
        int g = (q & 31) * 4;
        float4 avv = *reinterpret_cast<float4*>(sOut + 0 * 32 * VLD + n * VLD + g);
        float4 asv = *reinterpret_cast<float4*>(sOut + 1 * 32 * VLD + n * VLD + g);
        float4 ass = *reinterpret_cast<float4*>(sOut + 2 * 32 * VLD + n * VLD + g);
        float4 b0 = *reinterpret_cast<const float4*>(m2_b + g);
        float4 b1 = *reinterpret_cast<const float4*>(m2_b + 128 + g);
        float4 b2 = *reinterpret_cast<const float4*>(m2_b + 256 + g);
        avv.x += b0.x; avv.y += b0.y; avv.z += b0.z; avv.w += b0.w;
        asv.x += b1.x; asv.y += b1.y; asv.z += b1.z; asv.w += b1.w;
        ass.x += b2.x; ass.y += b2.y; ass.z += b2.z; ass.w += b2.w;
        float4 inn = *reinterpret_cast<float4*>(sInner + n * VLD + g);

        const float* nfr = nf + (size_t)n * 512;
        float* outr = op + (size_t)n * 512;

        float4 s = *reinterpret_cast<const float4*>(nfr + g);
        float4 os;
        os.x = s.x + asv.x * inn.x + ass.x;
        os.y = s.y + asv.y * inn.y + ass.y;
        os.z = s.z + asv.z * inn.z + ass.z;
        os.w = s.w + asv.w * inn.w + ass.w;
        *reinterpret_cast<float4*>(outr + g) = os;

        #pragma unroll
        for (int c = 0; c < 3; ++c) {
            float4 u = *reinterpret_cast<float4*>(sUv + c * 32 * VLD + n * VLD + g);
            float4 v = *reinterpret_cast<const float4*>(nfr + 128 + c * 128 + g);
            float4 ov;
            ov.x = v.x + avv.x * u.x;
            ov.y = v.y + avv.y * u.y;
            ov.z = v.z + avv.z * u.z;
            ov.w = v.w + avv.w * u.w;
            *reinterpret_cast<float4*>(outr + 128 + c * 128 + g) = ov;
        }
    }
}

extern "C" void kernel_launch(void* const* d_in, const int* in_sizes, int n_in,
                              void* d_out, int out_size) {
    const float* node_feat = (const float*)d_in[0];
    const float* U_w  = (const float*)d_in[1];
    const float* U_b  = (const float*)d_in[2];
    const float* V_w  = (const float*)d_in[3];
    const float* V_b  = (const float*)d_in[4];
    const float* m1_w = (const float*)d_in[5];
    const float* m1_b = (const float*)d_in[6];
    const float* m2_w = (const float*)d_in[7];
    const float* m2_b = (const float*)d_in[8];
    float* out = (float*)d_out;

    int N = in_sizes[0] / 512;

    prep_kernel<<<(49152 + 255) / 256, 256>>>(U_w, V_w, m1_w, m2_w);

    size_t smem_bytes = (size_t)(2 * 3 * 32 * VLD + 3 * 32 * VLD) * sizeof(float);
    cudaFuncSetAttribute(painn_kernel,
                         cudaFuncAttributeMaxDynamicSharedMemorySize,
                         (int)smem_bytes);
    painn_kernel<<<N / TM, NTHREADS, smem_bytes>>>(node_feat, U_b, V_b, m1_b, m2_b, out);
}

// round 8
// speedup vs baseline: 1.3967x; 1.3967x over previous
#include <cuda_runtime.h>
#include <mma.h>

using namespace nvcuda;

#define TM       16          // nodes per CTA
#define VLD      132         // smem leading dim (floats)
#define NTHREADS 256         // 8 warps

// RNA tf32-rounded weights (original layouts), filled by prep_kernel.
__device__ float g_U[128 * 128];
__device__ float g_V[128 * 128];
__device__ float g_m1[256 * 128];
__device__ float g_m2[128 * 384];

__device__ __forceinline__ float ftf32(float x) {
    float y;
    asm("cvt.rna.tf32.f32 %0, %1;" : "=f"(y) : "f"(x));
    return y;
}

__global__ void prep_kernel(const float* __restrict__ Uw,
                            const float* __restrict__ Vw,
                            const float* __restrict__ m1w,
                            const float* __restrict__ m2w) {
    int i = blockIdx.x * blockDim.x + threadIdx.x;
    if (i < 16384) { g_U[i] = ftf32(Uw[i]); g_V[i] = ftf32(Vw[i]); }
    if (i < 32768) g_m1[i] = ftf32(m1w[i]);
    if (i < 49152) g_m2[i] = ftf32(m2w[i]);
}

using FragA = wmma::fragment<wmma::matrix_a, 16, 16, 8, wmma::precision::tf32, wmma::row_major>;
using FragB = wmma::fragment<wmma::matrix_b, 16, 16, 8, wmma::precision::tf32, wmma::row_major>;
using FragC = wmma::fragment<wmma::accumulator, 16, 16, 8, float>;

__global__ __launch_bounds__(NTHREADS, 2)
void painn_kernel(const float* __restrict__ node_feat,
                  const float* __restrict__ U_b,
                  const float* __restrict__ V_b,
                  const float* __restrict__ m1_b,
                  const float* __restrict__ m2_b,
                  float* __restrict__ out) {
    extern __shared__ float smem[];
    float* sVec   = smem;                  // [3][16][VLD] vec rows (c*16+n), tf32 RNA
    float* sUv    = sVec   + 48 * VLD;     // [3][16][VLD] raw Uv -> biased Uv
    float* sOut   = sUv    + 48 * VLD;     // [3][16][VLD] stage-4 out; first 16xVLD = sSv temp
    float* sScal  = sOut   + 48 * VLD;     // [16][VLD] tf32 scalars
    float* sVn    = sScal  + 16 * VLD;     // [16][VLD] vn2 raw -> vn (tf32)
    float* sInner = sVn    + 16 * VLD;     // [16][VLD]
    float* sH     = sInner + 16 * VLD;     // [16][VLD]; holds sSu temp before stage 3
    float* sSu = sH;
    float* sSv = sOut;

    const int tid  = threadIdx.x;
    const int w    = tid >> 5;             // 0..7
    const size_t base = (size_t)blockIdx.x * (TM * 512);
    const float* nf = node_feat + base;
    float* op = out + base;

    // ---------- Stage 0: stage node tile into smem (tf32 RNA) ----------
    for (int q = tid; q < TM * 128; q += NTHREADS) {   // 2048 float4s
        int n  = q >> 7;
        int f0 = (q & 127) * 4;
        float4 v = *reinterpret_cast<const float4*>(nf + n * 512 + f0);
        v.x = ftf32(v.x); v.y = ftf32(v.y); v.z = ftf32(v.z); v.w = ftf32(v.w);
        float* dst;
        if (f0 < 128) {
            dst = sScal + n * VLD + f0;
        } else {
            int c = (f0 - 128) >> 7;
            int f = (f0 - 128) & 127;
            dst = sVec + (c * 16 + n) * VLD + f;
        }
        *reinterpret_cast<float4*>(dst) = v;
    }
    __syncthreads();

    // ---------- Stage 1: Uv/Vv GEMMs; warp owns col tile nt = w (0..7) ----------
    {
        const int nt = w;
        FragC aU[3], aV[3];
        #pragma unroll
        for (int c = 0; c < 3; ++c) {
            wmma::fill_fragment(aU[c], 0.0f);
            wmma::fill_fragment(aV[c], 0.0f);
        }
        #pragma unroll
        for (int k = 0; k < 16; ++k) {
            FragB bU, bV;
            wmma::load_matrix_sync(bU, g_U + k * 8 * 128 + nt * 16, 128);
            wmma::load_matrix_sync(bV, g_V + k * 8 * 128 + nt * 16, 128);
            #pragma unroll
            for (int c = 0; c < 3; ++c) {
                FragA af;
                wmma::load_matrix_sync(af, sVec + (c * 16) * VLD + k * 8, VLD);
                wmma::mma_sync(aU[c], af, bU, aU[c]);
                wmma::mma_sync(aV[c], af, bV, aV[c]);
            }
        }
        // layout-agnostic elementwise combines
        FragC fsu, fsv, finn, fvn2;
        #pragma unroll
        for (int i = 0; i < fsu.num_elements; ++i) {
            float u0 = aU[0].x[i], u1 = aU[1].x[i], u2 = aU[2].x[i];
            float v0 = aV[0].x[i], v1 = aV[1].x[i], v2 = aV[2].x[i];
            fsu.x[i]  = u0 + u1 + u2;
            fsv.x[i]  = v0 + v1 + v2;
            finn.x[i] = u0 * v0 + u1 * v1 + u2 * v2;
            fvn2.x[i] = v0 * v0 + v1 * v1 + v2 * v2;
        }
        #pragma unroll
        for (int c = 0; c < 3; ++c)
            wmma::store_matrix_sync(sUv + c * 16 * VLD + nt * 16, aU[c], VLD, wmma::mem_row_major);
        wmma::store_matrix_sync(sInner + nt * 16, finn, VLD, wmma::mem_row_major);
        wmma::store_matrix_sync(sVn    + nt * 16, fvn2, VLD, wmma::mem_row_major);
        wmma::store_matrix_sync(sSu    + nt * 16, fsu,  VLD, wmma::mem_row_major);
        wmma::store_matrix_sync(sSv    + nt * 16, fsv,  VLD, wmma::mem_row_major);
    }
    __syncthreads();

    // ---------- bias fix: Uv += ub; inner/vn2 corrected analytically ----------
    for (int q = tid; q < TM * 128; q += NTHREADS) {
        int n = q >> 7, g = q & 127;
        float ub = U_b[g], vb = V_b[g];
        float su = sSu[n * VLD + g];
        float sv = sSv[n * VLD + g];
        sUv[0 * 16 * VLD + n * VLD + g] += ub;
        sUv[1 * 16 * VLD + n * VLD + g] += ub;
        sUv[2 * 16 * VLD + n * VLD + g] += ub;
        sInner[n * VLD + g] += ub * sv + vb * su + 3.0f * ub * vb;
        float vn2 = sVn[n * VLD + g] + 2.0f * vb * sv + 3.0f * vb * vb;
        sVn[n * VLD + g] = ftf32(sqrtf(fmaxf(vn2, 0.0f)));
    }
    __syncthreads();   // sSu(sH), sSv(sOut) now dead

    // ---------- Stage 3: h = silu([Vn | scal] @ m1 + b), nt = w ----------
    {
        const int nt = w;
        FragC acc0, acc1;
        wmma::fill_fragment(acc0, 0.0f);
        wmma::fill_fragment(acc1, 0.0f);
        #pragma unroll
        for (int k = 0; k < 16; ++k) {
            FragA a0, a1;
            FragB b0, b1;
            wmma::load_matrix_sync(a0, sVn + k * 8, VLD);
            wmma::load_matrix_sync(b0, g_m1 + (k * 8) * 128 + nt * 16, 128);
            wmma::load_matrix_sync(a1, sScal + k * 8, VLD);
            wmma::load_matrix_sync(b1, g_m1 + (128 + k * 8) * 128 + nt * 16, 128);
            wmma::mma_sync(acc0, a0, b0, acc0);
            wmma::mma_sync(acc1, a1, b1, acc1);
        }
        #pragma unroll
        for (int i = 0; i < acc0.num_elements; ++i)
            acc0.x[i] += acc1.x[i];
        wmma::store_matrix_sync(sH + nt * 16, acc0, VLD, wmma::mem_row_major);
    }
    __syncthreads();

    // silu + round
    for (int q = tid; q < TM * 128; q += NTHREADS) {
        int n = q >> 7, g = q & 127;
        float x = sH[n * VLD + g] + m1_b[g];
        sH[n * VLD + g] = ftf32(x / (1.0f + __expf(-x)));
    }
    __syncthreads();

    // ---------- Stage 4: mlp_out = h @ m2 (24 col-tiles, 3 per warp) ----------
    #pragma unroll
    for (int p = 0; p < 3; ++p) {
        int nt_g = w + p * 8;              // 0..23
        FragC acc;
        wmma::fill_fragment(acc, 0.0f);
        #pragma unroll
        for (int k = 0; k < 16; ++k) {
            FragA a;
            FragB b;
            wmma::load_matrix_sync(a, sH + k * 8, VLD);
            wmma::load_matrix_sync(b, g_m2 + k * 8 * 384 + nt_g * 16, 384);
            wmma::mma_sync(acc, a, b, acc);
        }
        int blk  = nt_g >> 3;              // 0..2 -> a_vv, a_sv, a_ss
        int colc = (nt_g & 7) * 16;
        wmma::store_matrix_sync(sOut + blk * 16 * VLD + colc, acc, VLD, wmma::mem_row_major);
    }
    __syncthreads();

    // ---------- Epilogue: fp32 residual path ----------
    for (int q = tid; q < TM * 32; q += NTHREADS) {    // 512 quads
        int n = q >> 5;
        int g = (q & 31) * 4;
        float4 avv = *reinterpret_cast<float4*>(sOut + 0 * 16 * VLD + n * VLD + g);
        float4 asv = *reinterpret_cast<float4*>(sOut + 1 * 16 * VLD + n * VLD + g);
        float4 ass = *reinterpret_cast<float4*>(sOut + 2 * 16 * VLD + n * VLD + g);
        float4 b0 = *reinterpret_cast<const float4*>(m2_b + g);
        float4 b1 = *reinterpret_cast<const float4*>(m2_b + 128 + g);
        float4 b2 = *reinterpret_cast<const float4*>(m2_b + 256 + g);
        avv.x += b0.x; avv.y += b0.y; avv.z += b0.z; avv.w += b0.w;
        asv.x += b1.x; asv.y += b1.y; asv.z += b1.z; asv.w += b1.w;
        ass.x += b2.x; ass.y += b2.y; ass.z += b2.z; ass.w += b2.w;
        float4 inn = *reinterpret_cast<float4*>(sInner + n * VLD + g);

        const float* nfr = nf + (size_t)n * 512;
        float* outr = op + (size_t)n * 512;

        float4 s = *reinterpret_cast<const float4*>(nfr + g);
        float4 os;
        os.x = s.x + asv.x * inn.x + ass.x;
        os.y = s.y + asv.y * inn.y + ass.y;
        os.z = s.z + asv.z * inn.z + ass.z;
        os.w = s.w + asv.w * inn.w + ass.w;
        *reinterpret_cast<float4*>(outr + g) = os;

        #pragma unroll
        for (int c = 0; c < 3; ++c) {
            float4 u = *reinterpret_cast<float4*>(sUv + c * 16 * VLD + n * VLD + g);
            float4 v = *reinterpret_cast<const float4*>(nfr + 128 + c * 128 + g);
            float4 ov;
            ov.x = v.x + avv.x * u.x;
            ov.y = v.y + avv.y * u.y;
            ov.z = v.z + avv.z * u.z;
            ov.w = v.w + avv.w * u.w;
            *reinterpret_cast<float4*>(outr + 128 + c * 128 + g) = ov;
        }
    }
}

extern "C" void kernel_launch(void* const* d_in, const int* in_sizes, int n_in,
                              void* d_out, int out_size) {
    const float* node_feat = (const float*)d_in[0];
    const float* U_w  = (const float*)d_in[1];
    const float* U_b  = (const float*)d_in[2];
    const float* V_w  = (const float*)d_in[3];
    const float* V_b  = (const float*)d_in[4];
    const float* m1_w = (const float*)d_in[5];
    const float* m1_b = (const float*)d_in[6];
    const float* m2_w = (const float*)d_in[7];
    const float* m2_b = (const float*)d_in[8];
    float* out = (float*)d_out;

    int N = in_sizes[0] / 512;

    prep_kernel<<<(49152 + 255) / 256, 256>>>(U_w, V_w, m1_w, m2_w);

    size_t smem_bytes = (size_t)(208 * VLD) * sizeof(float);   // 109,824 B
    cudaFuncSetAttribute(painn_kernel,
                         cudaFuncAttributeMaxDynamicSharedMemorySize,
                         (int)smem_bytes);
    painn_kernel<<<N / TM, NTHREADS, smem_bytes>>>(node_feat, U_b, V_b, m1_b, m2_b, out);
}

// round 9
// speedup vs baseline: 2.3611x; 1.6904x over previous
#include <cuda_runtime.h>
#include <cstdint>

#define NTHREADS 256
#define TM 16

// Fragment-permuted, tf32-rounded weights.
__device__ __align__(16) float g_Up[16384];
__device__ __align__(16) float g_Vp[16384];
__device__ __align__(16) float g_m1p[32768];
__device__ __align__(16) float g_m2p[49152];

__device__ __forceinline__ float ftf32(float x) {
    float y;
    asm("cvt.rna.tf32.f32 %0, %1;" : "=f"(y) : "f"(x));
    return y;
}

// B-fragment-linear address for W[k][n] (K x N), n8-pairs packed per float4.
__device__ __forceinline__ int baddr(int k, int n, int N) {
    return (((k >> 3) * (N >> 4) + (n >> 4)) * 32 + (n & 7) * 4 + (k & 3)) * 4
           + ((n >> 3) & 1) * 2 + ((k >> 2) & 1);
}

// A-fragment-linear address within a 16-row x 8*KT column buffer for element (n,g).
__device__ __forceinline__ int aaddr(int n, int g) {
    return (g >> 3) * 128 + ((n & 7) * 4 + (g & 3)) * 4 + ((g >> 2) & 1) * 2 + (n >> 3);
}

__global__ void prep_kernel(const float* __restrict__ Uw, const float* __restrict__ Vw,
                            const float* __restrict__ m1w, const float* __restrict__ m2w) {
    int i = blockIdx.x * blockDim.x + threadIdx.x;
    if (i < 16384) {
        int k = i >> 7, n = i & 127;
        int a = baddr(k, n, 128);
        g_Up[a] = ftf32(Uw[i]);
        g_Vp[a] = ftf32(Vw[i]);
    }
    if (i < 32768) {
        int k = i >> 7, n = i & 127;
        g_m1p[baddr(k, n, 128)] = ftf32(m1w[i]);
    }
    if (i < 49152) {
        int k = i / 384, n = i % 384;
        g_m2p[baddr(k, n, 384)] = ftf32(m2w[i]);
    }
}

__device__ __forceinline__ void mma8(float* d, float4 a, float b0, float b1) {
    asm volatile(
        "mma.sync.aligned.m16n8k8.row.col.f32.tf32.tf32.f32 "
        "{%0,%1,%2,%3}, {%4,%5,%6,%7}, {%8,%9}, {%0,%1,%2,%3};"
        : "+f"(d[0]), "+f"(d[1]), "+f"(d[2]), "+f"(d[3])
        : "r"(__float_as_uint(a.x)), "r"(__float_as_uint(a.y)),
          "r"(__float_as_uint(a.z)), "r"(__float_as_uint(a.w)),
          "r"(__float_as_uint(b0)), "r"(__float_as_uint(b1)));
}

// smem float offsets
#define SVEC   0        // 6144: A-layout vec, frag (c*16+kt); [0:2048] reused as stage-3 C out
#define SSCAL  6144     // 2048: A-layout scalars
#define SUV    8192     // 6144: C-layout raw Uv, frag (c*16+f)
#define SOUT   14336    // 6144: C-layout stage-4 out; aliases: [0:2048]=vn2C, [2048:4096]=svC, [4096:6144]=vnA
#define SINNER 20480    // 2048: C-layout inner (raw -> corrected)
#define SH     22528    // 2048: A-layout h; also suC temp
#define SMEM_FLOATS 24576

__global__ __launch_bounds__(NTHREADS, 2)
void painn_kernel(const float* __restrict__ node_feat,
                  const float* __restrict__ U_b,
                  const float* __restrict__ V_b,
                  const float* __restrict__ m1_b,
                  const float* __restrict__ m2_b,
                  float* __restrict__ out) {
    extern __shared__ float smem[];
    float* sVec   = smem + SVEC;
    float* sScal  = smem + SSCAL;
    float* sUv    = smem + SUV;
    float* sOut   = smem + SOUT;
    float* sInner = smem + SINNER;
    float* sH     = smem + SH;
    float* sC3    = smem + SVEC;        // stage-3 C out (sVec dead)
    float* sVnC   = sOut;               // raw vn2, C-layout
    float* sSv    = sOut + 2048;        // raw sum_c Vv, C-layout
    float* sVnA   = sOut + 4096;        // vn, A-layout
    float* sSu    = sH;                 // raw sum_c Uv, C-layout

    const int tid  = threadIdx.x;
    const int w    = tid >> 5;          // 0..7
    const int lane = tid & 31;
    const size_t base = (size_t)blockIdx.x * (TM * 512);
    const float* nf = node_feat + base;
    float* op = out + base;

    // ---------- Stage 0: stage node tile, A-fragment layout, tf32 RNA ----------
    for (int q = tid; q < TM * 128; q += NTHREADS) {
        int n  = q >> 7;
        int f0 = (q & 127) * 4;
        float4 v = *reinterpret_cast<const float4*>(nf + n * 512 + f0);
        v.x = ftf32(v.x); v.y = ftf32(v.y); v.z = ftf32(v.z); v.w = ftf32(v.w);
        float* dstb;
        int g;
        if (f0 < 128) { dstb = sScal; g = f0; }
        else {
            int c = (f0 - 128) >> 7;
            g = (f0 - 128) & 127;
            dstb = sVec + c * 16 * 128;
        }
        int r = ((g >> 2) & 1) * 2 + (n >> 3);
        int b0 = (g >> 3) * 128 + ((n & 7) * 4) * 4 + r;   // g&3 == 0
        dstb[b0 + 0]  = v.x;
        dstb[b0 + 4]  = v.y;
        dstb[b0 + 8]  = v.z;
        dstb[b0 + 12] = v.w;
    }
    __syncthreads();

    // ---------- Stage 1: Uv/Vv GEMMs, warp owns n16-pair w ----------
    {
        float accU[2][3][4], accV[2][3][4];
        #pragma unroll
        for (int s = 0; s < 2; ++s)
            #pragma unroll
            for (int c = 0; c < 3; ++c)
                #pragma unroll
                for (int r = 0; r < 4; ++r) { accU[s][c][r] = 0.f; accV[s][c][r] = 0.f; }

        #pragma unroll 4
        for (int kt = 0; kt < 16; ++kt) {
            float4 a0 = *reinterpret_cast<float4*>(sVec + (0 * 16 + kt) * 128 + lane * 4);
            float4 a1 = *reinterpret_cast<float4*>(sVec + (1 * 16 + kt) * 128 + lane * 4);
            float4 a2 = *reinterpret_cast<float4*>(sVec + (2 * 16 + kt) * 128 + lane * 4);
            float4 bu = *reinterpret_cast<const float4*>(g_Up + ((kt * 8 + w) * 32 + lane) * 4);
            float4 bv = *reinterpret_cast<const float4*>(g_Vp + ((kt * 8 + w) * 32 + lane) * 4);
            mma8(accU[0][0], a0, bu.x, bu.y); mma8(accU[1][0], a0, bu.z, bu.w);
            mma8(accU[0][1], a1, bu.x, bu.y); mma8(accU[1][1], a1, bu.z, bu.w);
            mma8(accU[0][2], a2, bu.x, bu.y); mma8(accU[1][2], a2, bu.z, bu.w);
            mma8(accV[0][0], a0, bv.x, bv.y); mma8(accV[1][0], a0, bv.z, bv.w);
            mma8(accV[0][1], a1, bv.x, bv.y); mma8(accV[1][1], a1, bv.z, bv.w);
            mma8(accV[0][2], a2, bv.x, bv.y); mma8(accV[1][2], a2, bv.z, bv.w);
        }

        #pragma unroll
        for (int s = 0; s < 2; ++s) {
            int fr = w * 2 + s;
            float fsu[4], fsv[4], finn[4], fvn2[4];
            #pragma unroll
            for (int r = 0; r < 4; ++r) {
                float u0 = accU[s][0][r], u1 = accU[s][1][r], u2 = accU[s][2][r];
                float v0 = accV[s][0][r], v1 = accV[s][1][r], v2 = accV[s][2][r];
                fsu[r]  = u0 + u1 + u2;
                fsv[r]  = v0 + v1 + v2;
                finn[r] = u0 * v0 + u1 * v1 + u2 * v2;
                fvn2[r] = v0 * v0 + v1 * v1 + v2 * v2;
            }
            #pragma unroll
            for (int c = 0; c < 3; ++c)
                *reinterpret_cast<float4*>(sUv + (c * 16 + fr) * 128 + lane * 4) =
                    make_float4(accU[s][c][0], accU[s][c][1], accU[s][c][2], accU[s][c][3]);
            *reinterpret_cast<float4*>(sInner + fr * 128 + lane * 4) = make_float4(finn[0], finn[1], finn[2], finn[3]);
            *reinterpret_cast<float4*>(sVnC   + fr * 128 + lane * 4) = make_float4(fvn2[0], fvn2[1], fvn2[2], fvn2[3]);
            *reinterpret_cast<float4*>(sSu    + fr * 128 + lane * 4) = make_float4(fsu[0], fsu[1], fsu[2], fsu[3]);
            *reinterpret_cast<float4*>(sSv    + fr * 128 + lane * 4) = make_float4(fsv[0], fsv[1], fsv[2], fsv[3]);
        }
    }
    __syncthreads();

    // ---------- Stage 2: analytic bias correction; vn -> A-layout ----------
    for (int slot = tid; slot < 512; slot += NTHREADS) {
        int f = slot >> 5, ln = slot & 31;
        int gid = ln >> 2, tig = ln & 3;
        int bofs = f * 128 + ln * 4;
        float4 su  = *reinterpret_cast<float4*>(sSu + bofs);
        float4 sv  = *reinterpret_cast<float4*>(sSv + bofs);
        float4 inn = *reinterpret_cast<float4*>(sInner + bofs);
        float4 vnc = *reinterpret_cast<float4*>(sVnC + bofs);
        float* sup = reinterpret_cast<float*>(&su);
        float* svp = reinterpret_cast<float*>(&sv);
        float* inp = reinterpret_cast<float*>(&inn);
        float* vcp = reinterpret_cast<float*>(&vnc);
        #pragma unroll
        for (int r = 0; r < 4; ++r) {
            int col = f * 8 + 2 * tig + (r & 1);
            int row = gid + 8 * (r >> 1);
            float ub = U_b[col], vb = V_b[col];
            inp[r] = inp[r] + ub * svp[r] + vb * sup[r] + 3.0f * ub * vb;
            float vn2 = vcp[r] + 2.0f * vb * svp[r] + 3.0f * vb * vb;
            sVnA[aaddr(row, col)] = ftf32(sqrtf(fmaxf(vn2, 0.0f)));
        }
        *reinterpret_cast<float4*>(sInner + bofs) = inn;
    }
    __syncthreads();

    // ---------- Stage 3: C3 = [Vn | scal] @ m1 ----------
    {
        float acc[2][4];
        #pragma unroll
        for (int s = 0; s < 2; ++s)
            #pragma unroll
            for (int r = 0; r < 4; ++r) acc[s][r] = 0.f;
        #pragma unroll 4
        for (int kt = 0; kt < 16; ++kt) {
            float4 a = *reinterpret_cast<float4*>(sVnA + kt * 128 + lane * 4);
            float4 b = *reinterpret_cast<const float4*>(g_m1p + ((kt * 8 + w) * 32 + lane) * 4);
            mma8(acc[0], a, b.x, b.y);
            mma8(acc[1], a, b.z, b.w);
        }
        #pragma unroll 4
        for (int kt = 0; kt < 16; ++kt) {
            float4 a = *reinterpret_cast<float4*>(sScal + kt * 128 + lane * 4);
            float4 b = *reinterpret_cast<const float4*>(g_m1p + (((kt + 16) * 8 + w) * 32 + lane) * 4);
            mma8(acc[0], a, b.x, b.y);
            mma8(acc[1], a, b.z, b.w);
        }
        #pragma unroll
        for (int s = 0; s < 2; ++s)
            *reinterpret_cast<float4*>(sC3 + (w * 2 + s) * 128 + lane * 4) =
                make_float4(acc[s][0], acc[s][1], acc[s][2], acc[s][3]);
    }
    __syncthreads();

    // ---------- silu: C3 -> h (A-layout) ----------
    for (int slot = tid; slot < 512; slot += NTHREADS) {
        int f = slot >> 5, ln = slot & 31;
        int gid = ln >> 2, tig = ln & 3;
        float4 x4 = *reinterpret_cast<float4*>(sC3 + f * 128 + ln * 4);
        float* xp = reinterpret_cast<float*>(&x4);
        #pragma unroll
        for (int r = 0; r < 4; ++r) {
            int col = f * 8 + 2 * tig + (r & 1);
            int row = gid + 8 * (r >> 1);
            float x = xp[r] + m1_b[col];
            sH[aaddr(row, col)] = ftf32(x / (1.0f + __expf(-x)));
        }
    }
    __syncthreads();

    // ---------- Stage 4: mlp_out = h @ m2 (24 n16-pairs, 3 per warp) ----------
    #pragma unroll
    for (int p = 0; p < 3; ++p) {
        int pair = w + p * 8;
        float acc[2][4];
        #pragma unroll
        for (int s = 0; s < 2; ++s)
            #pragma unroll
            for (int r = 0; r < 4; ++r) acc[s][r] = 0.f;
        #pragma unroll 4
        for (int kt = 0; kt < 16; ++kt) {
            float4 a = *reinterpret_cast<float4*>(sH + kt * 128 + lane * 4);
            float4 b = *reinterpret_cast<const float4*>(g_m2p + ((kt * 24 + pair) * 32 + lane) * 4);
            mma8(acc[0], a, b.x, b.y);
            mma8(acc[1], a, b.z, b.w);
        }
        #pragma unroll
        for (int s = 0; s < 2; ++s)
            *reinterpret_cast<float4*>(sOut + (pair * 2 + s) * 128 + lane * 4) =
                make_float4(acc[s][0], acc[s][1], acc[s][2], acc[s][3]);
    }
    __syncthreads();

    // ---------- Epilogue: fp32 residual path (C-fragment coordinates) ----------
    for (int slot = tid; slot < 2048; slot += NTHREADS) {
        int part = slot >> 9;              // 0 = scalar, 1..3 = vec c
        int f  = (slot >> 5) & 15;
        int ln = slot & 31;
        int gid = ln >> 2, tig = ln & 3;
        int colb = f * 8 + 2 * tig;
        if (part == 0) {
            float4 asv4 = *reinterpret_cast<float4*>(sOut + (16 + f) * 128 + ln * 4);
            float4 ass4 = *reinterpret_cast<float4*>(sOut + (32 + f) * 128 + ln * 4);
            float4 inn4 = *reinterpret_cast<float4*>(sInner + f * 128 + ln * 4);
            float* asv = reinterpret_cast<float*>(&asv4);
            float* ass = reinterpret_cast<float*>(&ass4);
            float* inn = reinterpret_cast<float*>(&inn4);
            float2 b1 = *reinterpret_cast<const float2*>(m2_b + 128 + colb);
            float2 b2 = *reinterpret_cast<const float2*>(m2_b + 256 + colb);
            #pragma unroll
            for (int hh = 0; hh < 2; ++hh) {
                int row = gid + 8 * hh;
                float2 s = *reinterpret_cast<const float2*>(nf + row * 512 + colb);
                float2 o;
                o.x = s.x + (asv[hh * 2 + 0] + b1.x) * inn[hh * 2 + 0] + ass[hh * 2 + 0] + b2.x;
                o.y = s.y + (asv[hh * 2 + 1] + b1.y) * inn[hh * 2 + 1] + ass[hh * 2 + 1] + b2.y;
                *reinterpret_cast<float2*>(op + row * 512 + colb) = o;
            }
        } else {
            int c = part - 1;
            float4 avv4 = *reinterpret_cast<float4*>(sOut + f * 128 + ln * 4);
            float4 u4   = *reinterpret_cast<float4*>(sUv + (c * 16 + f) * 128 + ln * 4);
            float* avv = reinterpret_cast<float*>(&avv4);
            float* uu  = reinterpret_cast<float*>(&u4);
            float2 b0  = *reinterpret_cast<const float2*>(m2_b + colb);
            float2 ub2 = *reinterpret_cast<const float2*>(U_b + colb);
            #pragma unroll
            for (int hh = 0; hh < 2; ++hh) {
                int row = gid + 8 * hh;
                const float* src = nf + row * 512 + 128 + c * 128 + colb;
                float2 v = *reinterpret_cast<const float2*>(src);
                float2 o;
                o.x = v.x + (avv[hh * 2 + 0] + b0.x) * (uu[hh * 2 + 0] + ub2.x);
                o.y = v.y + (avv[hh * 2 + 1] + b0.y) * (uu[hh * 2 + 1] + ub2.y);
                *reinterpret_cast<float2*>(op + row * 512 + 128 + c * 128 + colb) = o;
            }
        }
    }
}

extern "C" void kernel_launch(void* const* d_in, const int* in_sizes, int n_in,
                              void* d_out, int out_size) {
    const float* node_feat = (const float*)d_in[0];
    const float* U_w  = (const float*)d_in[1];
    const float* U_b  = (const float*)d_in[2];
    const float* V_w  = (const float*)d_in[3];
    const float* V_b  = (const float*)d_in[4];
    const float* m1_w = (const float*)d_in[5];
    const float* m1_b = (const float*)d_in[6];
    const float* m2_w = (const float*)d_in[7];
    const float* m2_b = (const float*)d_in[8];
    float* out = (float*)d_out;

    int N = in_sizes[0] / 512;

    prep_kernel<<<(49152 + 255) / 256, 256>>>(U_w, V_w, m1_w, m2_w);

    size_t smem_bytes = SMEM_FLOATS * sizeof(float);   // 98,304 B
    cudaFuncSetAttribute(painn_kernel,
                         cudaFuncAttributeMaxDynamicSharedMemorySize,
                         (int)smem_bytes);
    painn_kernel<<<N / TM, NTHREADS, smem_bytes>>>(node_feat, U_b, V_b, m1_b, m2_b, out);
}

// round 10
// speedup vs baseline: 2.7021x; 1.1444x over previous
#include <cuda_runtime.h>
#include <cstdint>

#define NTHREADS 256
#define TM 16

// Fragment-permuted, tf32-rounded weights.
__device__ __align__(16) float g_Up[16384];
__device__ __align__(16) float g_Vp[16384];
__device__ __align__(16) float g_m1p[32768];
__device__ __align__(16) float g_m2p[49152];

__device__ __forceinline__ float ftf32(float x) {
    float y;
    asm("cvt.rna.tf32.f32 %0, %1;" : "=f"(y) : "f"(x));
    return y;
}

// B-fragment-linear address for W[k][n] (K x N), n8-pairs packed per float4.
__device__ __forceinline__ int baddr(int k, int n, int N) {
    return (((k >> 3) * (N >> 4) + (n >> 4)) * 32 + (n & 7) * 4 + (k & 3)) * 4
           + ((n >> 3) & 1) * 2 + ((k >> 2) & 1);
}

// A-fragment-linear address within a 16-row x 128-col buffer for element (n,g).
__device__ __forceinline__ int aaddr(int n, int g) {
    return (g >> 3) * 128 + ((n & 7) * 4 + (g & 3)) * 4 + ((g >> 2) & 1) * 2 + (n >> 3);
}

__global__ void prep_kernel(const float* __restrict__ Uw, const float* __restrict__ Vw,
                            const float* __restrict__ m1w, const float* __restrict__ m2w) {
    int i = blockIdx.x * blockDim.x + threadIdx.x;
    if (i < 16384) {
        int k = i >> 7, n = i & 127;
        int a = baddr(k, n, 128);
        g_Up[a] = ftf32(Uw[i]);
        g_Vp[a] = ftf32(Vw[i]);
    }
    if (i < 32768) {
        int k = i >> 7, n = i & 127;
        g_m1p[baddr(k, n, 128)] = ftf32(m1w[i]);
    }
    if (i < 49152) {
        int k = i / 384, n = i % 384;
        g_m2p[baddr(k, n, 384)] = ftf32(m2w[i]);
    }
}

__device__ __forceinline__ void mma8(float* d, float4 a, float b0, float b1) {
    asm volatile(
        "mma.sync.aligned.m16n8k8.row.col.f32.tf32.tf32.f32 "
        "{%0,%1,%2,%3}, {%4,%5,%6,%7}, {%8,%9}, {%0,%1,%2,%3};"
        : "+f"(d[0]), "+f"(d[1]), "+f"(d[2]), "+f"(d[3])
        : "r"(__float_as_uint(a.x)), "r"(__float_as_uint(a.y)),
          "r"(__float_as_uint(a.z)), "r"(__float_as_uint(a.w)),
          "r"(__float_as_uint(b0)), "r"(__float_as_uint(b1)));
}

// smem float offsets
#define SVEC   0        // 6144: A-layout vec tiles, frame (c*16+kt)
#define SSCAL  6144     // 2048: A-layout scalars
#define SUV    8192     // 6144: C-layout raw Uv, frag (c*16+f)
#define SINNER 14336    // 2048: C-layout corrected inner
#define SVNA   16384    // 2048: A-layout vn
#define SH     18432    // 2048: A-layout h
#define SMEM_FLOATS 20480

__global__ __launch_bounds__(NTHREADS, 2)
void painn_kernel(const float* __restrict__ node_feat,
                  const float* __restrict__ U_b,
                  const float* __restrict__ V_b,
                  const float* __restrict__ m1_b,
                  const float* __restrict__ m2_b,
                  float* __restrict__ out) {
    extern __shared__ float smem[];
    float* sVec   = smem + SVEC;
    float* sScal  = smem + SSCAL;
    float* sUv    = smem + SUV;
    float* sInner = smem + SINNER;
    float* sVnA   = smem + SVNA;
    float* sH     = smem + SH;

    const int tid  = threadIdx.x;
    const int w    = tid >> 5;          // 0..7
    const int lane = tid & 31;
    const int tig  = lane & 3;
    const int gid  = lane >> 2;
    const size_t base = (size_t)blockIdx.x * (TM * 512);
    const float* nf = node_feat + base;
    float* op = out + base;

    // ---------- Stage 0: stage node tile, A-fragment layout, tf32 RNA ----------
    for (int q = tid; q < TM * 128; q += NTHREADS) {
        int n  = q >> 7;
        int f0 = (q & 127) * 4;
        float4 v = *reinterpret_cast<const float4*>(nf + n * 512 + f0);
        v.x = ftf32(v.x); v.y = ftf32(v.y); v.z = ftf32(v.z); v.w = ftf32(v.w);
        float* dstb;
        int g;
        if (f0 < 128) { dstb = sScal; g = f0; }
        else {
            int c = (f0 - 128) >> 7;
            g = (f0 - 128) & 127;
            dstb = sVec + c * 16 * 128;
        }
        int r = ((g >> 2) & 1) * 2 + (n >> 3);
        int b0 = (g >> 3) * 128 + ((n & 7) * 4) * 4 + r;   // g&3 == 0
        dstb[b0 + 0]  = v.x;
        dstb[b0 + 4]  = v.y;
        dstb[b0 + 8]  = v.z;
        dstb[b0 + 12] = v.w;
    }
    __syncthreads();

    // ---------- Stage 1: Uv/Vv GEMMs + fused bias-correction tail ----------
    {
        float accU[2][3][4], accV[2][3][4];
        #pragma unroll
        for (int s = 0; s < 2; ++s)
            #pragma unroll
            for (int c = 0; c < 3; ++c)
                #pragma unroll
                for (int r = 0; r < 4; ++r) { accU[s][c][r] = 0.f; accV[s][c][r] = 0.f; }

        #pragma unroll 4
        for (int kt = 0; kt < 16; ++kt) {
            float4 a0 = *reinterpret_cast<float4*>(sVec + (0 * 16 + kt) * 128 + lane * 4);
            float4 a1 = *reinterpret_cast<float4*>(sVec + (1 * 16 + kt) * 128 + lane * 4);
            float4 a2 = *reinterpret_cast<float4*>(sVec + (2 * 16 + kt) * 128 + lane * 4);
            float4 bu = *reinterpret_cast<const float4*>(g_Up + ((kt * 8 + w) * 32 + lane) * 4);
            float4 bv = *reinterpret_cast<const float4*>(g_Vp + ((kt * 8 + w) * 32 + lane) * 4);
            mma8(accU[0][0], a0, bu.x, bu.y); mma8(accU[1][0], a0, bu.z, bu.w);
            mma8(accU[0][1], a1, bu.x, bu.y); mma8(accU[1][1], a1, bu.z, bu.w);
            mma8(accU[0][2], a2, bu.x, bu.y); mma8(accU[1][2], a2, bu.z, bu.w);
            mma8(accV[0][0], a0, bv.x, bv.y); mma8(accV[1][0], a0, bv.z, bv.w);
            mma8(accV[0][1], a1, bv.x, bv.y); mma8(accV[1][1], a1, bv.z, bv.w);
            mma8(accV[0][2], a2, bv.x, bv.y); mma8(accV[1][2], a2, bv.z, bv.w);
        }

        #pragma unroll
        for (int s = 0; s < 2; ++s) {
            int fr = w * 2 + s;
            int colbase = fr * 8 + 2 * tig;
            float2 ub2 = *reinterpret_cast<const float2*>(U_b + colbase);
            float2 vb2 = *reinterpret_cast<const float2*>(V_b + colbase);
            float finn[4];
            #pragma unroll
            for (int r = 0; r < 4; ++r) {
                float u0 = accU[s][0][r], u1 = accU[s][1][r], u2 = accU[s][2][r];
                float v0 = accV[s][0][r], v1 = accV[s][1][r], v2 = accV[s][2][r];
                float fsu  = u0 + u1 + u2;
                float fsv  = v0 + v1 + v2;
                float inn  = u0 * v0 + u1 * v1 + u2 * v2;
                float vn2  = v0 * v0 + v1 * v1 + v2 * v2;
                float ub = (r & 1) ? ub2.y : ub2.x;
                float vb = (r & 1) ? vb2.y : vb2.x;
                finn[r] = inn + ub * fsv + vb * fsu + 3.0f * ub * vb;
                float vn2c = vn2 + 2.0f * vb * fsv + 3.0f * vb * vb;
                int col = colbase + (r & 1);
                int row = gid + 8 * (r >> 1);
                sVnA[aaddr(row, col)] = ftf32(sqrtf(fmaxf(vn2c, 0.0f)));
            }
            #pragma unroll
            for (int c = 0; c < 3; ++c)
                *reinterpret_cast<float4*>(sUv + (c * 16 + fr) * 128 + lane * 4) =
                    make_float4(accU[s][c][0], accU[s][c][1], accU[s][c][2], accU[s][c][3]);
            *reinterpret_cast<float4*>(sInner + fr * 128 + lane * 4) =
                make_float4(finn[0], finn[1], finn[2], finn[3]);
        }
    }
    __syncthreads();

    // ---------- Stage 3: h = silu([Vn | scal] @ m1 + b), fused silu tail ----------
    {
        float acc[2][4];
        #pragma unroll
        for (int s = 0; s < 2; ++s)
            #pragma unroll
            for (int r = 0; r < 4; ++r) acc[s][r] = 0.f;
        #pragma unroll 4
        for (int kt = 0; kt < 16; ++kt) {
            float4 a = *reinterpret_cast<float4*>(sVnA + kt * 128 + lane * 4);
            float4 b = *reinterpret_cast<const float4*>(g_m1p + ((kt * 8 + w) * 32 + lane) * 4);
            mma8(acc[0], a, b.x, b.y);
            mma8(acc[1], a, b.z, b.w);
        }
        #pragma unroll 4
        for (int kt = 0; kt < 16; ++kt) {
            float4 a = *reinterpret_cast<float4*>(sScal + kt * 128 + lane * 4);
            float4 b = *reinterpret_cast<const float4*>(g_m1p + (((kt + 16) * 8 + w) * 32 + lane) * 4);
            mma8(acc[0], a, b.x, b.y);
            mma8(acc[1], a, b.z, b.w);
        }
        #pragma unroll
        for (int s = 0; s < 2; ++s) {
            int fr = w * 2 + s;
            int colbase = fr * 8 + 2 * tig;
            float2 mb2 = *reinterpret_cast<const float2*>(m1_b + colbase);
            #pragma unroll
            for (int r = 0; r < 4; ++r) {
                float x = acc[s][r] + ((r & 1) ? mb2.y : mb2.x);
                int col = colbase + (r & 1);
                int row = gid + 8 * (r >> 1);
                sH[aaddr(row, col)] = ftf32(x / (1.0f + __expf(-x)));
            }
        }
    }
    __syncthreads();

    // ---------- Stage 4: mlp_out = h @ m2 + fused epilogue ----------
    // Warp owns pairs {w, w+8, w+16} = a_vv / a_sv / a_ss at the SAME 16 cols.
    {
        float acc[3][2][4];
        #pragma unroll
        for (int p = 0; p < 3; ++p)
            #pragma unroll
            for (int s = 0; s < 2; ++s)
                #pragma unroll
                for (int r = 0; r < 4; ++r) acc[p][s][r] = 0.f;

        #pragma unroll 4
        for (int kt = 0; kt < 16; ++kt) {
            float4 a = *reinterpret_cast<float4*>(sH + kt * 128 + lane * 4);
            #pragma unroll
            for (int p = 0; p < 3; ++p) {
                int pair = w + p * 8;
                float4 b = *reinterpret_cast<const float4*>(g_m2p + ((kt * 24 + pair) * 32 + lane) * 4);
                mma8(acc[p][0], a, b.x, b.y);
                mma8(acc[p][1], a, b.z, b.w);
            }
        }

        // epilogue: C-fragment geometry matches sInner/sUv fragments exactly
        #pragma unroll
        for (int s = 0; s < 2; ++s) {
            int fr = w * 2 + s;
            int colb = fr * 8 + 2 * tig;       // global col in [0,128)
            float4 inn4 = *reinterpret_cast<float4*>(sInner + fr * 128 + lane * 4);
            const float* innp = reinterpret_cast<const float*>(&inn4);
            float2 b0 = *reinterpret_cast<const float2*>(m2_b + colb);
            float2 b1 = *reinterpret_cast<const float2*>(m2_b + 128 + colb);
            float2 b2 = *reinterpret_cast<const float2*>(m2_b + 256 + colb);
            float2 ub2 = *reinterpret_cast<const float2*>(U_b + colb);

            // scalar residual
            #pragma unroll
            for (int hh = 0; hh < 2; ++hh) {
                int row = gid + 8 * hh;
                float2 sres = *reinterpret_cast<const float2*>(nf + row * 512 + colb);
                float2 o;
                o.x = sres.x + (acc[1][s][hh * 2 + 0] + b1.x) * innp[hh * 2 + 0]
                    + acc[2][s][hh * 2 + 0] + b2.x;
                o.y = sres.y + (acc[1][s][hh * 2 + 1] + b1.y) * innp[hh * 2 + 1]
                    + acc[2][s][hh * 2 + 1] + b2.y;
                *reinterpret_cast<float2*>(op + row * 512 + colb) = o;
            }
            // vector residuals
            #pragma unroll
            for (int c = 0; c < 3; ++c) {
                float4 u4 = *reinterpret_cast<float4*>(sUv + (c * 16 + fr) * 128 + lane * 4);
                const float* up = reinterpret_cast<const float*>(&u4);
                #pragma unroll
                for (int hh = 0; hh < 2; ++hh) {
                    int row = gid + 8 * hh;
                    const float* src = nf + row * 512 + 128 + c * 128 + colb;
                    float2 v = *reinterpret_cast<const float2*>(src);
                    float2 o;
                    o.x = v.x + (acc[0][s][hh * 2 + 0] + b0.x) * (up[hh * 2 + 0] + ub2.x);
                    o.y = v.y + (acc[0][s][hh * 2 + 1] + b0.y) * (up[hh * 2 + 1] + ub2.y);
                    *reinterpret_cast<float2*>(op + row * 512 + 128 + c * 128 + colb) = o;
                }
            }
        }
    }
}

extern "C" void kernel_launch(void* const* d_in, const int* in_sizes, int n_in,
                              void* d_out, int out_size) {
    const float* node_feat = (const float*)d_in[0];
    const float* U_w  = (const float*)d_in[1];
    const float* U_b  = (const float*)d_in[2];
    const float* V_w  = (const float*)d_in[3];
    const float* V_b  = (const float*)d_in[4];
    const float* m1_w = (const float*)d_in[5];
    const float* m1_b = (const float*)d_in[6];
    const float* m2_w = (const float*)d_in[7];
    const float* m2_b = (const float*)d_in[8];
    float* out = (float*)d_out;

    int N = in_sizes[0] / 512;

    prep_kernel<<<(49152 + 255) / 256, 256>>>(U_w, V_w, m1_w, m2_w);

    size_t smem_bytes = SMEM_FLOATS * sizeof(float);   // 81,920 B
    cudaFuncSetAttribute(painn_kernel,
                         cudaFuncAttributeMaxDynamicSharedMemorySize,
                         (int)smem_bytes);
    painn_kernel<<<N / TM, NTHREADS, smem_bytes>>>(node_feat, U_b, V_b, m1_b, m2_b, out);
}

// round 11
// speedup vs baseline: 2.9776x; 1.1020x over previous
#include <cuda_runtime.h>
#include <cstdint>

#define NTHREADS 256
#define TM 32

// Fragment-permuted, tf32-rounded weights.
__device__ __align__(16) float g_Up[16384];
__device__ __align__(16) float g_Vp[16384];
__device__ __align__(16) float g_m1p[32768];
__device__ __align__(16) float g_m2p[49152];

__device__ __forceinline__ float ftf32(float x) {
    float y;
    asm("cvt.rna.tf32.f32 %0, %1;" : "=f"(y) : "f"(x));
    return y;
}

// B-fragment-linear address for W[k][n] (K x N), n8-pairs packed per float4.
__device__ __forceinline__ int baddr(int k, int n, int N) {
    return (((k >> 3) * (N >> 4) + (n >> 4)) * 32 + (n & 7) * 4 + (k & 3)) * 4
           + ((n >> 3) & 1) * 2 + ((k >> 2) & 1);
}

// A-fragment-linear address within a 16-row x 128-col tile for element (n,g).
__device__ __forceinline__ int aaddr(int n, int g) {
    return (g >> 3) * 128 + ((n & 7) * 4 + (g & 3)) * 4 + ((g >> 2) & 1) * 2 + (n >> 3);
}

__global__ void prep_kernel(const float* __restrict__ Uw, const float* __restrict__ Vw,
                            const float* __restrict__ m1w, const float* __restrict__ m2w) {
    int i = blockIdx.x * blockDim.x + threadIdx.x;
    if (i < 16384) {
        int k = i >> 7, n = i & 127;
        int a = baddr(k, n, 128);
        g_Up[a] = ftf32(Uw[i]);
        g_Vp[a] = ftf32(Vw[i]);
    }
    if (i < 32768) {
        int k = i >> 7, n = i & 127;
        g_m1p[baddr(k, n, 128)] = ftf32(m1w[i]);
    }
    if (i < 49152) {
        int k = i / 384, n = i % 384;
        g_m2p[baddr(k, n, 384)] = ftf32(m2w[i]);
    }
}

__device__ __forceinline__ void mma8(float* d, float4 a, float b0, float b1) {
    asm volatile(
        "mma.sync.aligned.m16n8k8.row.col.f32.tf32.tf32.f32 "
        "{%0,%1,%2,%3}, {%4,%5,%6,%7}, {%8,%9}, {%0,%1,%2,%3};"
        : "+f"(d[0]), "+f"(d[1]), "+f"(d[2]), "+f"(d[3])
        : "r"(__float_as_uint(a.x)), "r"(__float_as_uint(a.y)),
          "r"(__float_as_uint(a.z)), "r"(__float_as_uint(a.w)),
          "r"(__float_as_uint(b0)), "r"(__float_as_uint(b1)));
}

// smem float offsets (tiles of 2048 floats = 16 rows x 128 cols, A/C frag layout)
#define SVEC   0        // 12288: vec tiles (c*2+mt); after stage-1 aliased as sUv
#define SSCAL  12288    // 4096: scalar tiles (mt)
#define SVNA   16384    // 4096: vn tiles (mt), A-layout
#define SH     20480    // 4096: h tiles (mt), A-layout
#define SMEM_FLOATS 24576

__global__ __launch_bounds__(NTHREADS, 2)
void painn_kernel(const float* __restrict__ node_feat,
                  const float* __restrict__ U_b,
                  const float* __restrict__ V_b,
                  const float* __restrict__ m1_b,
                  const float* __restrict__ m2_b,
                  float* __restrict__ out) {
    extern __shared__ float smem[];
    float* sVec  = smem + SVEC;
    float* sUv   = smem + SVEC;         // alias, valid after stage-1 barrier
    float* sScal = smem + SSCAL;
    float* sVnA  = smem + SVNA;
    float* sH    = smem + SH;

    const int tid  = threadIdx.x;
    const int w    = tid >> 5;          // 0..7
    const int lane = tid & 31;
    const int tig  = lane & 3;
    const int gid  = lane >> 2;
    const size_t base = (size_t)blockIdx.x * (TM * 512);
    const float* nf = node_feat + base;
    float* op = out + base;

    // ---------- Stage 0: stage 32-node tile, A-fragment layout, tf32 RNA ----------
    for (int q = tid; q < TM * 128; q += NTHREADS) {
        int n  = q >> 7;                // 0..31
        int f0 = (q & 127) * 4;
        int mt = n >> 4;
        int nl = n & 15;
        float4 v = *reinterpret_cast<const float4*>(nf + n * 512 + f0);
        v.x = ftf32(v.x); v.y = ftf32(v.y); v.z = ftf32(v.z); v.w = ftf32(v.w);
        float* dstb;
        int g;
        if (f0 < 128) { dstb = sScal + mt * 2048; g = f0; }
        else {
            int c = (f0 - 128) >> 7;
            g = (f0 - 128) & 127;
            dstb = sVec + (c * 2 + mt) * 2048;
        }
        int r = ((g >> 2) & 1) * 2 + (nl >> 3);
        int b0 = (g >> 3) * 128 + (nl & 7) * 16 + r;   // g&3 == 0
        dstb[b0 + 0]  = v.x;
        dstb[b0 + 4]  = v.y;
        dstb[b0 + 8]  = v.z;
        dstb[b0 + 12] = v.w;
    }
    __syncthreads();

    float inner[2][2][4];   // [mt][s][r], persists to epilogue

    // ---------- Stage 1: Uv/Vv GEMMs; B reused across 2 m-tiles ----------
    {
        float accU[2][2][3][4], accV[2][2][3][4];   // [mt][s][c][r]
        #pragma unroll
        for (int mt = 0; mt < 2; ++mt)
            #pragma unroll
            for (int s = 0; s < 2; ++s)
                #pragma unroll
                for (int c = 0; c < 3; ++c)
                    #pragma unroll
                    for (int r = 0; r < 4; ++r) { accU[mt][s][c][r] = 0.f; accV[mt][s][c][r] = 0.f; }

        #pragma unroll 2
        for (int kt = 0; kt < 16; ++kt) {
            float4 bu = *reinterpret_cast<const float4*>(g_Up + ((kt * 8 + w) * 32 + lane) * 4);
            float4 bv = *reinterpret_cast<const float4*>(g_Vp + ((kt * 8 + w) * 32 + lane) * 4);
            #pragma unroll
            for (int mt = 0; mt < 2; ++mt) {
                float4 a0 = *reinterpret_cast<float4*>(sVec + (0 * 2 + mt) * 2048 + kt * 128 + lane * 4);
                float4 a1 = *reinterpret_cast<float4*>(sVec + (1 * 2 + mt) * 2048 + kt * 128 + lane * 4);
                float4 a2 = *reinterpret_cast<float4*>(sVec + (2 * 2 + mt) * 2048 + kt * 128 + lane * 4);
                mma8(accU[mt][0][0], a0, bu.x, bu.y); mma8(accU[mt][1][0], a0, bu.z, bu.w);
                mma8(accU[mt][0][1], a1, bu.x, bu.y); mma8(accU[mt][1][1], a1, bu.z, bu.w);
                mma8(accU[mt][0][2], a2, bu.x, bu.y); mma8(accU[mt][1][2], a2, bu.z, bu.w);
                mma8(accV[mt][0][0], a0, bv.x, bv.y); mma8(accV[mt][1][0], a0, bv.z, bv.w);
                mma8(accV[mt][0][1], a1, bv.x, bv.y); mma8(accV[mt][1][1], a1, bv.z, bv.w);
                mma8(accV[mt][0][2], a2, bv.x, bv.y); mma8(accV[mt][1][2], a2, bv.z, bv.w);
            }
        }
        __syncthreads();   // all warps done reading sVec; safe to overwrite as sUv

        #pragma unroll
        for (int mt = 0; mt < 2; ++mt) {
            #pragma unroll
            for (int s = 0; s < 2; ++s) {
                int fr = w * 2 + s;
                int colbase = fr * 8 + 2 * tig;
                float2 ub2 = *reinterpret_cast<const float2*>(U_b + colbase);
                float2 vb2 = *reinterpret_cast<const float2*>(V_b + colbase);
                #pragma unroll
                for (int r = 0; r < 4; ++r) {
                    float u0 = accU[mt][s][0][r], u1 = accU[mt][s][1][r], u2 = accU[mt][s][2][r];
                    float v0 = accV[mt][s][0][r], v1 = accV[mt][s][1][r], v2 = accV[mt][s][2][r];
                    float fsu = u0 + u1 + u2;
                    float fsv = v0 + v1 + v2;
                    float inn = u0 * v0 + u1 * v1 + u2 * v2;
                    float vn2 = v0 * v0 + v1 * v1 + v2 * v2;
                    float ub = (r & 1) ? ub2.y : ub2.x;
                    float vb = (r & 1) ? vb2.y : vb2.x;
                    inner[mt][s][r] = inn + ub * fsv + vb * fsu + 3.0f * ub * vb;
                    float vn2c = vn2 + 2.0f * vb * fsv + 3.0f * vb * vb;
                    int col = colbase + (r & 1);
                    int rowl = gid + 8 * (r >> 1);
                    sVnA[mt * 2048 + aaddr(rowl, col)] = ftf32(sqrtf(fmaxf(vn2c, 0.0f)));
                }
                #pragma unroll
                for (int c = 0; c < 3; ++c)
                    *reinterpret_cast<float4*>(sUv + (c * 2 + mt) * 2048 + fr * 128 + lane * 4) =
                        make_float4(accU[mt][s][c][0], accU[mt][s][c][1],
                                    accU[mt][s][c][2], accU[mt][s][c][3]);
            }
        }
    }
    __syncthreads();

    // ---------- Stage 3: h = silu([Vn | scal] @ m1 + b); B reused across m-tiles ----------
    {
        float acc[2][2][4];   // [mt][s][r]
        #pragma unroll
        for (int mt = 0; mt < 2; ++mt)
            #pragma unroll
            for (int s = 0; s < 2; ++s)
                #pragma unroll
                for (int r = 0; r < 4; ++r) acc[mt][s][r] = 0.f;
        #pragma unroll 4
        for (int kt = 0; kt < 16; ++kt) {
            float4 b = *reinterpret_cast<const float4*>(g_m1p + ((kt * 8 + w) * 32 + lane) * 4);
            #pragma unroll
            for (int mt = 0; mt < 2; ++mt) {
                float4 a = *reinterpret_cast<float4*>(sVnA + mt * 2048 + kt * 128 + lane * 4);
                mma8(acc[mt][0], a, b.x, b.y);
                mma8(acc[mt][1], a, b.z, b.w);
            }
        }
        #pragma unroll 4
        for (int kt = 0; kt < 16; ++kt) {
            float4 b = *reinterpret_cast<const float4*>(g_m1p + (((kt + 16) * 8 + w) * 32 + lane) * 4);
            #pragma unroll
            for (int mt = 0; mt < 2; ++mt) {
                float4 a = *reinterpret_cast<float4*>(sScal + mt * 2048 + kt * 128 + lane * 4);
                mma8(acc[mt][0], a, b.x, b.y);
                mma8(acc[mt][1], a, b.z, b.w);
            }
        }
        #pragma unroll
        for (int mt = 0; mt < 2; ++mt) {
            #pragma unroll
            for (int s = 0; s < 2; ++s) {
                int fr = w * 2 + s;
                int colbase = fr * 8 + 2 * tig;
                float2 mb2 = *reinterpret_cast<const float2*>(m1_b + colbase);
                #pragma unroll
                for (int r = 0; r < 4; ++r) {
                    float x = acc[mt][s][r] + ((r & 1) ? mb2.y : mb2.x);
                    int col = colbase + (r & 1);
                    int rowl = gid + 8 * (r >> 1);
                    sH[mt * 2048 + aaddr(rowl, col)] = ftf32(x / (1.0f + __expf(-x)));
                }
            }
        }
    }
    __syncthreads();

    // ---------- Stage 4: mlp_out = h @ m2 + fused epilogue ----------
    {
        float acc[2][3][2][4];   // [mt][p][s][r]
        #pragma unroll
        for (int mt = 0; mt < 2; ++mt)
            #pragma unroll
            for (int p = 0; p < 3; ++p)
                #pragma unroll
                for (int s = 0; s < 2; ++s)
                    #pragma unroll
                    for (int r = 0; r < 4; ++r) acc[mt][p][s][r] = 0.f;

        #pragma unroll 4
        for (int kt = 0; kt < 16; ++kt) {
            float4 a0 = *reinterpret_cast<float4*>(sH + 0 * 2048 + kt * 128 + lane * 4);
            float4 a1 = *reinterpret_cast<float4*>(sH + 1 * 2048 + kt * 128 + lane * 4);
            #pragma unroll
            for (int p = 0; p < 3; ++p) {
                int pair = w + p * 8;
                float4 b = *reinterpret_cast<const float4*>(g_m2p + ((kt * 24 + pair) * 32 + lane) * 4);
                mma8(acc[0][p][0], a0, b.x, b.y); mma8(acc[0][p][1], a0, b.z, b.w);
                mma8(acc[1][p][0], a1, b.x, b.y); mma8(acc[1][p][1], a1, b.z, b.w);
            }
        }

        // fused epilogue; C-fragment geometry matches inner/Uv fragments
        #pragma unroll
        for (int mt = 0; mt < 2; ++mt) {
            #pragma unroll
            for (int s = 0; s < 2; ++s) {
                int fr = w * 2 + s;
                int colb = fr * 8 + 2 * tig;
                float2 b0 = *reinterpret_cast<const float2*>(m2_b + colb);
                float2 b1 = *reinterpret_cast<const float2*>(m2_b + 128 + colb);
                float2 b2 = *reinterpret_cast<const float2*>(m2_b + 256 + colb);
                float2 ub2 = *reinterpret_cast<const float2*>(U_b + colb);

                #pragma unroll
                for (int hh = 0; hh < 2; ++hh) {
                    int row = mt * 16 + gid + 8 * hh;
                    float2 sres = *reinterpret_cast<const float2*>(nf + row * 512 + colb);
                    float2 o;
                    o.x = sres.x + (acc[mt][1][s][hh * 2 + 0] + b1.x) * inner[mt][s][hh * 2 + 0]
                        + acc[mt][2][s][hh * 2 + 0] + b2.x;
                    o.y = sres.y + (acc[mt][1][s][hh * 2 + 1] + b1.y) * inner[mt][s][hh * 2 + 1]
                        + acc[mt][2][s][hh * 2 + 1] + b2.y;
                    *reinterpret_cast<float2*>(op + row * 512 + colb) = o;
                }
                #pragma unroll
                for (int c = 0; c < 3; ++c) {
                    float4 u4 = *reinterpret_cast<float4*>(sUv + (c * 2 + mt) * 2048 + fr * 128 + lane * 4);
                    const float* up = reinterpret_cast<const float*>(&u4);
                    #pragma unroll
                    for (int hh = 0; hh < 2; ++hh) {
                        int row = mt * 16 + gid + 8 * hh;
                        const float* src = nf + row * 512 + 128 + c * 128 + colb;
                        float2 v = *reinterpret_cast<const float2*>(src);
                        float2 o;
                        o.x = v.x + (acc[mt][0][s][hh * 2 + 0] + b0.x) * (up[hh * 2 + 0] + ub2.x);
                        o.y = v.y + (acc[mt][0][s][hh * 2 + 1] + b0.y) * (up[hh * 2 + 1] + ub2.y);
                        *reinterpret_cast<float2*>(op + row * 512 + 128 + c * 128 + colb) = o;
                    }
                }
            }
        }
    }
}

extern "C" void kernel_launch(void* const* d_in, const int* in_sizes, int n_in,
                              void* d_out, int out_size) {
    const float* node_feat = (const float*)d_in[0];
    const float* U_w  = (const float*)d_in[1];
    const float* U_b  = (const float*)d_in[2];
    const float* V_w  = (const float*)d_in[3];
    const float* V_b  = (const float*)d_in[4];
    const float* m1_w = (const float*)d_in[5];
    const float* m1_b = (const float*)d_in[6];
    const float* m2_w = (const float*)d_in[7];
    const float* m2_b = (const float*)d_in[8];
    float* out = (float*)d_out;

    int N = in_sizes[0] / 512;

    prep_kernel<<<(49152 + 255) / 256, 256>>>(U_w, V_w, m1_w, m2_w);

    size_t smem_bytes = SMEM_FLOATS * sizeof(float);   // 98,304 B
    cudaFuncSetAttribute(painn_kernel,
                         cudaFuncAttributeMaxDynamicSharedMemorySize,
                         (int)smem_bytes);
    painn_kernel<<<N / TM, NTHREADS, smem_bytes>>>(node_feat, U_b, V_b, m1_b, m2_b, out);
}

// round 12
// speedup vs baseline: 3.2720x; 1.0989x over previous
#include <cuda_runtime.h>
#include <cstdint>

#define NTHREADS 256
#define TM 32
#define FS  132            // floats per kt-frame (padded from 128)
#define TSZ 2112           // 16 * FS, floats per 16x128 fragment tile

// Fragment-permuted, tf32-rounded weights.
__device__ __align__(16) float g_Up[16384];
__device__ __align__(16) float g_Vp[16384];
__device__ __align__(16) float g_m1p[32768];
__device__ __align__(16) float g_m2p[49152];

__device__ __forceinline__ float ftf32(float x) {
    float y;
    asm("cvt.rna.tf32.f32 %0, %1;" : "=f"(y) : "f"(x));
    return y;
}

// B-fragment-linear address for W[k][n] (K x N), n8-pairs packed per float4.
__device__ __forceinline__ int baddr(int k, int n, int N) {
    return (((k >> 3) * (N >> 4) + (n >> 4)) * 32 + (n & 7) * 4 + (k & 3)) * 4
           + ((n >> 3) & 1) * 2 + ((k >> 2) & 1);
}

// A-fragment-linear address within a padded 16x128 tile for element (n,g).
__device__ __forceinline__ int aaddr(int n, int g) {
    return (g >> 3) * FS + ((n & 7) * 4 + (g & 3)) * 4 + ((g >> 2) & 1) * 2 + (n >> 3);
}

__global__ void prep_kernel(const float* __restrict__ Uw, const float* __restrict__ Vw,
                            const float* __restrict__ m1w, const float* __restrict__ m2w) {
    int i = blockIdx.x * blockDim.x + threadIdx.x;
    if (i < 16384) {
        int k = i >> 7, n = i & 127;
        int a = baddr(k, n, 128);
        g_Up[a] = ftf32(Uw[i]);
        g_Vp[a] = ftf32(Vw[i]);
    }
    if (i < 32768) {
        int k = i >> 7, n = i & 127;
        g_m1p[baddr(k, n, 128)] = ftf32(m1w[i]);
    }
    if (i < 49152) {
        int k = i / 384, n = i % 384;
        g_m2p[baddr(k, n, 384)] = ftf32(m2w[i]);
    }
}

__device__ __forceinline__ void mma8(float* d, float4 a, float b0, float b1) {
    asm volatile(
        "mma.sync.aligned.m16n8k8.row.col.f32.tf32.tf32.f32 "
        "{%0,%1,%2,%3}, {%4,%5,%6,%7}, {%8,%9}, {%0,%1,%2,%3};"
        : "+f"(d[0]), "+f"(d[1]), "+f"(d[2]), "+f"(d[3])
        : "r"(__float_as_uint(a.x)), "r"(__float_as_uint(a.y)),
          "r"(__float_as_uint(a.z)), "r"(__float_as_uint(a.w)),
          "r"(__float_as_uint(b0)), "r"(__float_as_uint(b1)));
}

// smem float offsets (padded tiles of TSZ floats)
#define SVEC   0                 // 6 tiles (c*2+mt); aliased as sUv after stage 1
#define SSCAL  (6 * TSZ)         // 2 tiles (mt)
#define SVNA   (8 * TSZ)         // 2 tiles (mt)
#define SH     (10 * TSZ)        // 2 tiles (mt)
#define SMEM_FLOATS (12 * TSZ)   // 25344 floats = 101376 B

__global__ __launch_bounds__(NTHREADS, 2)
void painn_kernel(const float* __restrict__ node_feat,
                  const float* __restrict__ U_b,
                  const float* __restrict__ V_b,
                  const float* __restrict__ m1_b,
                  const float* __restrict__ m2_b,
                  float* __restrict__ out) {
    extern __shared__ float smem[];
    float* sVec  = smem + SVEC;
    float* sUv   = smem + SVEC;         // alias, valid after stage-1 barrier
    float* sScal = smem + SSCAL;
    float* sVnA  = smem + SVNA;
    float* sH    = smem + SH;

    const int tid  = threadIdx.x;
    const int w    = tid >> 5;          // 0..7
    const int lane = tid & 31;
    const int tig  = lane & 3;
    const int gid  = lane >> 2;
    const size_t base = (size_t)blockIdx.x * (TM * 512);
    const float* nf = node_feat + base;
    float* op = out + base;

    // ---------- Stage 0: stage 32-node tile, A-fragment layout, tf32 RNA ----------
    for (int q = tid; q < TM * 128; q += NTHREADS) {
        int n  = q >> 7;                // 0..31
        int f0 = (q & 127) * 4;
        int mt = n >> 4;
        int nl = n & 15;
        float4 v = *reinterpret_cast<const float4*>(nf + n * 512 + f0);
        v.x = ftf32(v.x); v.y = ftf32(v.y); v.z = ftf32(v.z); v.w = ftf32(v.w);
        float* dstb;
        int g;
        if (f0 < 128) { dstb = sScal + mt * TSZ; g = f0; }
        else {
            int c = (f0 - 128) >> 7;
            g = (f0 - 128) & 127;
            dstb = sVec + (c * 2 + mt) * TSZ;
        }
        int r = ((g >> 2) & 1) * 2 + (nl >> 3);
        int b0 = (g >> 3) * FS + (nl & 7) * 16 + r;   // g&3 == 0
        dstb[b0 + 0]  = v.x;
        dstb[b0 + 4]  = v.y;
        dstb[b0 + 8]  = v.z;
        dstb[b0 + 12] = v.w;
    }
    __syncthreads();

    float inner[2][2][4];   // [mt][s][r], persists to epilogue

    // ---------- Stage 1: Uv/Vv GEMMs; B reused across 2 m-tiles ----------
    {
        float accU[2][2][3][4], accV[2][2][3][4];   // [mt][s][c][r]
        #pragma unroll
        for (int mt = 0; mt < 2; ++mt)
            #pragma unroll
            for (int s = 0; s < 2; ++s)
                #pragma unroll
                for (int c = 0; c < 3; ++c)
                    #pragma unroll
                    for (int r = 0; r < 4; ++r) { accU[mt][s][c][r] = 0.f; accV[mt][s][c][r] = 0.f; }

        #pragma unroll 2
        for (int kt = 0; kt < 16; ++kt) {
            float4 bu = *reinterpret_cast<const float4*>(g_Up + ((kt * 8 + w) * 32 + lane) * 4);
            float4 bv = *reinterpret_cast<const float4*>(g_Vp + ((kt * 8 + w) * 32 + lane) * 4);
            #pragma unroll
            for (int mt = 0; mt < 2; ++mt) {
                float4 a0 = *reinterpret_cast<float4*>(sVec + (0 * 2 + mt) * TSZ + kt * FS + lane * 4);
                float4 a1 = *reinterpret_cast<float4*>(sVec + (1 * 2 + mt) * TSZ + kt * FS + lane * 4);
                float4 a2 = *reinterpret_cast<float4*>(sVec + (2 * 2 + mt) * TSZ + kt * FS + lane * 4);
                mma8(accU[mt][0][0], a0, bu.x, bu.y); mma8(accU[mt][1][0], a0, bu.z, bu.w);
                mma8(accU[mt][0][1], a1, bu.x, bu.y); mma8(accU[mt][1][1], a1, bu.z, bu.w);
                mma8(accU[mt][0][2], a2, bu.x, bu.y); mma8(accU[mt][1][2], a2, bu.z, bu.w);
                mma8(accV[mt][0][0], a0, bv.x, bv.y); mma8(accV[mt][1][0], a0, bv.z, bv.w);
                mma8(accV[mt][0][1], a1, bv.x, bv.y); mma8(accV[mt][1][1], a1, bv.z, bv.w);
                mma8(accV[mt][0][2], a2, bv.x, bv.y); mma8(accV[mt][1][2], a2, bv.z, bv.w);
            }
        }
        __syncthreads();   // all warps done reading sVec; safe to overwrite as sUv

        #pragma unroll
        for (int mt = 0; mt < 2; ++mt) {
            #pragma unroll
            for (int s = 0; s < 2; ++s) {
                int fr = w * 2 + s;
                int colbase = fr * 8 + 2 * tig;
                float2 ub2 = *reinterpret_cast<const float2*>(U_b + colbase);
                float2 vb2 = *reinterpret_cast<const float2*>(V_b + colbase);
                #pragma unroll
                for (int r = 0; r < 4; ++r) {
                    float u0 = accU[mt][s][0][r], u1 = accU[mt][s][1][r], u2 = accU[mt][s][2][r];
                    float v0 = accV[mt][s][0][r], v1 = accV[mt][s][1][r], v2 = accV[mt][s][2][r];
                    float fsu = u0 + u1 + u2;
                    float fsv = v0 + v1 + v2;
                    float inn = u0 * v0 + u1 * v1 + u2 * v2;
                    float vn2 = v0 * v0 + v1 * v1 + v2 * v2;
                    float ub = (r & 1) ? ub2.y : ub2.x;
                    float vb = (r & 1) ? vb2.y : vb2.x;
                    inner[mt][s][r] = inn + ub * fsv + vb * fsu + 3.0f * ub * vb;
                    float vn2c = vn2 + 2.0f * vb * fsv + 3.0f * vb * vb;
                    int col = colbase + (r & 1);
                    int rowl = gid + 8 * (r >> 1);
                    sVnA[mt * TSZ + aaddr(rowl, col)] = ftf32(sqrtf(fmaxf(vn2c, 0.0f)));
                }
                #pragma unroll
                for (int c = 0; c < 3; ++c)
                    *reinterpret_cast<float4*>(sUv + (c * 2 + mt) * TSZ + fr * FS + lane * 4) =
                        make_float4(accU[mt][s][c][0], accU[mt][s][c][1],
                                    accU[mt][s][c][2], accU[mt][s][c][3]);
            }
        }
    }
    __syncthreads();

    // ---------- Stage 3: h = silu([Vn | scal] @ m1 + b); B software-pipelined ----------
    {
        float acc[2][2][4];   // [mt][s][r]
        #pragma unroll
        for (int mt = 0; mt < 2; ++mt)
            #pragma unroll
            for (int s = 0; s < 2; ++s)
                #pragma unroll
                for (int r = 0; r < 4; ++r) acc[mt][s][r] = 0.f;

        float4 b = *reinterpret_cast<const float4*>(g_m1p + ((0 * 8 + w) * 32 + lane) * 4);
        #pragma unroll
        for (int kt = 0; kt < 32; ++kt) {
            float4 bn;
            if (kt < 31)
                bn = *reinterpret_cast<const float4*>(g_m1p + (((kt + 1) * 8 + w) * 32 + lane) * 4);
            float* abase = (kt < 16) ? sVnA : sScal;
            int ktl = kt & 15;
            #pragma unroll
            for (int mt = 0; mt < 2; ++mt) {
                float4 a = *reinterpret_cast<float4*>(abase + mt * TSZ + ktl * FS + lane * 4);
                mma8(acc[mt][0], a, b.x, b.y);
                mma8(acc[mt][1], a, b.z, b.w);
            }
            b = bn;
        }
        #pragma unroll
        for (int mt = 0; mt < 2; ++mt) {
            #pragma unroll
            for (int s = 0; s < 2; ++s) {
                int fr = w * 2 + s;
                int colbase = fr * 8 + 2 * tig;
                float2 mb2 = *reinterpret_cast<const float2*>(m1_b + colbase);
                #pragma unroll
                for (int r = 0; r < 4; ++r) {
                    float x = acc[mt][s][r] + ((r & 1) ? mb2.y : mb2.x);
                    int col = colbase + (r & 1);
                    int rowl = gid + 8 * (r >> 1);
                    sH[mt * TSZ + aaddr(rowl, col)] = ftf32(x / (1.0f + __expf(-x)));
                }
            }
        }
    }
    __syncthreads();

    // ---------- Stage 4: mlp_out = h @ m2 + fused epilogue; B software-pipelined ----------
    {
        float acc[2][3][2][4];   // [mt][p][s][r]
        #pragma unroll
        for (int mt = 0; mt < 2; ++mt)
            #pragma unroll
            for (int p = 0; p < 3; ++p)
                #pragma unroll
                for (int s = 0; s < 2; ++s)
                    #pragma unroll
                    for (int r = 0; r < 4; ++r) acc[mt][p][s][r] = 0.f;

        float4 b[3], bn[3];
        #pragma unroll
        for (int p = 0; p < 3; ++p)
            b[p] = *reinterpret_cast<const float4*>(g_m2p + ((0 * 24 + w + p * 8) * 32 + lane) * 4);

        #pragma unroll 4
        for (int kt = 0; kt < 16; ++kt) {
            if (kt < 15) {
                #pragma unroll
                for (int p = 0; p < 3; ++p)
                    bn[p] = *reinterpret_cast<const float4*>(
                        g_m2p + (((kt + 1) * 24 + w + p * 8) * 32 + lane) * 4);
            }
            float4 a0 = *reinterpret_cast<float4*>(sH + 0 * TSZ + kt * FS + lane * 4);
            float4 a1 = *reinterpret_cast<float4*>(sH + 1 * TSZ + kt * FS + lane * 4);
            #pragma unroll
            for (int p = 0; p < 3; ++p) {
                mma8(acc[0][p][0], a0, b[p].x, b[p].y); mma8(acc[0][p][1], a0, b[p].z, b[p].w);
                mma8(acc[1][p][0], a1, b[p].x, b[p].y); mma8(acc[1][p][1], a1, b[p].z, b[p].w);
            }
            #pragma unroll
            for (int p = 0; p < 3; ++p) b[p] = bn[p];
        }

        // fused epilogue; C-fragment geometry matches inner/Uv fragments
        #pragma unroll
        for (int mt = 0; mt < 2; ++mt) {
            #pragma unroll
            for (int s = 0; s < 2; ++s) {
                int fr = w * 2 + s;
                int colb = fr * 8 + 2 * tig;
                float2 b0 = *reinterpret_cast<const float2*>(m2_b + colb);
                float2 b1 = *reinterpret_cast<const float2*>(m2_b + 128 + colb);
                float2 b2 = *reinterpret_cast<const float2*>(m2_b + 256 + colb);
                float2 ub2 = *reinterpret_cast<const float2*>(U_b + colb);

                #pragma unroll
                for (int hh = 0; hh < 2; ++hh) {
                    int row = mt * 16 + gid + 8 * hh;
                    float2 sres = *reinterpret_cast<const float2*>(nf + row * 512 + colb);
                    float2 o;
                    o.x = sres.x + (acc[mt][1][s][hh * 2 + 0] + b1.x) * inner[mt][s][hh * 2 + 0]
                        + acc[mt][2][s][hh * 2 + 0] + b2.x;
                    o.y = sres.y + (acc[mt][1][s][hh * 2 + 1] + b1.y) * inner[mt][s][hh * 2 + 1]
                        + acc[mt][2][s][hh * 2 + 1] + b2.y;
                    *reinterpret_cast<float2*>(op + row * 512 + colb) = o;
                }
                #pragma unroll
                for (int c = 0; c < 3; ++c) {
                    float4 u4 = *reinterpret_cast<float4*>(sUv + (c * 2 + mt) * TSZ + fr * FS + lane * 4);
                    const float* up = reinterpret_cast<const float*>(&u4);
                    #pragma unroll
                    for (int hh = 0; hh < 2; ++hh) {
                        int row = mt * 16 + gid + 8 * hh;
                        const float* src = nf + row * 512 + 128 + c * 128 + colb;
                        float2 v = *reinterpret_cast<const float2*>(src);
                        float2 o;
                        o.x = v.x + (acc[mt][0][s][hh * 2 + 0] + b0.x) * (up[hh * 2 + 0] + ub2.x);
                        o.y = v.y + (acc[mt][0][s][hh * 2 + 1] + b0.y) * (up[hh * 2 + 1] + ub2.y);
                        *reinterpret_cast<float2*>(op + row * 512 + 128 + c * 128 + colb) = o;
                    }
                }
            }
        }
    }
}

extern "C" void kernel_launch(void* const* d_in, const int* in_sizes, int n_in,
                              void* d_out, int out_size) {
    const float* node_feat = (const float*)d_in[0];
    const float* U_w  = (const float*)d_in[1];
    const float* U_b  = (const float*)d_in[2];
    const float* V_w  = (const float*)d_in[3];
    const float* V_b  = (const float*)d_in[4];
    const float* m1_w = (const float*)d_in[5];
    const float* m1_b = (const float*)d_in[6];
    const float* m2_w = (const float*)d_in[7];
    const float* m2_b = (const float*)d_in[8];
    float* out = (float*)d_out;

    int N = in_sizes[0] / 512;

    prep_kernel<<<(49152 + 255) / 256, 256>>>(U_w, V_w, m1_w, m2_w);

    size_t smem_bytes = SMEM_FLOATS * sizeof(float);   // 101,376 B
    cudaFuncSetAttribute(painn_kernel,
                         cudaFuncAttributeMaxDynamicSharedMemorySize,
                         (int)smem_bytes);
    painn_kernel<<<N / TM, NTHREADS, smem_bytes>>>(node_feat, U_b, V_b, m1_b, m2_b, out);
}

// round 14
// speedup vs baseline: 3.5002x; 1.0697x over previous
#include <cuda_runtime.h>
#include <cstdint>

#define NTHREADS 256
#define TM 32
#define FS  132            // floats per kt-frame (padded from 128)
#define TSZ 2112           // 16 * FS, floats per 16x128 fragment tile

// Fragment-permuted, tf32-rounded weights.
__device__ __align__(16) float g_Up[16384];
__device__ __align__(16) float g_Vp[16384];
__device__ __align__(16) float g_m1p[32768];
__device__ __align__(16) float g_m2p[49152];

__device__ __forceinline__ float ftf32(float x) {
    float y;
    asm("cvt.rna.tf32.f32 %0, %1;" : "=f"(y) : "f"(x));
    return y;
}

// B-fragment-linear address for W[k][n] (K x N), n8-pairs packed per float4.
__device__ __forceinline__ int baddr(int k, int n, int N) {
    return (((k >> 3) * (N >> 4) + (n >> 4)) * 32 + (n & 7) * 4 + (k & 3)) * 4
           + ((n >> 3) & 1) * 2 + ((k >> 2) & 1);
}

// A-fragment-linear address within a padded 16x128 tile for element (n,g).
__device__ __forceinline__ int aaddr(int n, int g) {
    return (g >> 3) * FS + ((n & 7) * 4 + (g & 3)) * 4 + ((g >> 2) & 1) * 2 + (n >> 3);
}

__global__ void prep_kernel(const float* __restrict__ Uw, const float* __restrict__ Vw,
                            const float* __restrict__ m1w, const float* __restrict__ m2w) {
    int i = blockIdx.x * blockDim.x + threadIdx.x;
    if (i < 16384) {
        int k = i >> 7, n = i & 127;
        int a = baddr(k, n, 128);
        g_Up[a] = ftf32(Uw[i]);
        g_Vp[a] = ftf32(Vw[i]);
    }
    if (i < 32768) {
        int k = i >> 7, n = i & 127;
        g_m1p[baddr(k, n, 128)] = ftf32(m1w[i]);
    }
    if (i < 49152) {
        int k = i / 384, n = i % 384;
        g_m2p[baddr(k, n, 384)] = ftf32(m2w[i]);
    }
}

__device__ __forceinline__ void mma8(float* d, float4 a, float b0, float b1) {
    asm volatile(
        "mma.sync.aligned.m16n8k8.row.col.f32.tf32.tf32.f32 "
        "{%0,%1,%2,%3}, {%4,%5,%6,%7}, {%8,%9}, {%0,%1,%2,%3};"
        : "+f"(d[0]), "+f"(d[1]), "+f"(d[2]), "+f"(d[3])
        : "r"(__float_as_uint(a.x)), "r"(__float_as_uint(a.y)),
          "r"(__float_as_uint(a.z)), "r"(__float_as_uint(a.w)),
          "r"(__float_as_uint(b0)), "r"(__float_as_uint(b1)));
}

// smem float offsets (padded tiles of TSZ floats)
#define SVEC   0                 // 6 tiles (c*2+mt); aliased as sUv after stage 1
#define SSCAL  (6 * TSZ)         // 2 tiles (mt)
#define SVNA   (8 * TSZ)         // 2 tiles (mt)
#define SH     (10 * TSZ)        // 2 tiles (mt)
#define SMEM_FLOATS (12 * TSZ)   // 25344 floats = 101376 B

__global__ __launch_bounds__(NTHREADS, 2)
void painn_kernel(const float* __restrict__ node_feat,
                  const float* __restrict__ U_b,
                  const float* __restrict__ V_b,
                  const float* __restrict__ m1_b,
                  const float* __restrict__ m2_b,
                  float* __restrict__ out) {
    extern __shared__ float smem[];
    float* sVec  = smem + SVEC;
    float* sUv   = smem + SVEC;         // alias, valid after stage-1 barrier
    float* sScal = smem + SSCAL;
    float* sVnA  = smem + SVNA;
    float* sH    = smem + SH;

    const int tid  = threadIdx.x;
    const int w    = tid >> 5;          // 0..7
    const int lane = tid & 31;
    const int tig  = lane & 3;
    const int gid  = lane >> 2;
    const size_t base = (size_t)blockIdx.x * (TM * 512);
    const float* nf = node_feat + base;
    float* op = out + base;

    // ---------- Stage 0: stage 32-node tile, A-fragment layout, tf32 RNA ----------
    #pragma unroll
    for (int it = 0; it < TM * 128 / NTHREADS; ++it) {
        int q  = tid + it * NTHREADS;
        int n  = q >> 7;                // 0..31
        int f0 = (q & 127) * 4;
        int mt = n >> 4;
        int nl = n & 15;
        float4 v = *reinterpret_cast<const float4*>(nf + n * 512 + f0);
        v.x = ftf32(v.x); v.y = ftf32(v.y); v.z = ftf32(v.z); v.w = ftf32(v.w);
        float* dstb;
        int g;
        if (f0 < 128) { dstb = sScal + mt * TSZ; g = f0; }
        else {
            int c = (f0 - 128) >> 7;
            g = (f0 - 128) & 127;
            dstb = sVec + (c * 2 + mt) * TSZ;
        }
        int r = ((g >> 2) & 1) * 2 + (nl >> 3);
        int b0 = (g >> 3) * FS + (nl & 7) * 16 + r;   // g&3 == 0
        dstb[b0 + 0]  = v.x;
        dstb[b0 + 4]  = v.y;
        dstb[b0 + 8]  = v.z;
        dstb[b0 + 12] = v.w;
    }
    __syncthreads();

    float inner[2][2][4];   // [mt][s][r], persists to epilogue

    // ---------- Stage 1: Uv/Vv GEMMs; B reused across 2 m-tiles, B prefetched ----------
    {
        float accU[2][2][3][4], accV[2][2][3][4];   // [mt][s][c][r]
        #pragma unroll
        for (int mt = 0; mt < 2; ++mt)
            #pragma unroll
            for (int s = 0; s < 2; ++s)
                #pragma unroll
                for (int c = 0; c < 3; ++c)
                    #pragma unroll
                    for (int r = 0; r < 4; ++r) { accU[mt][s][c][r] = 0.f; accV[mt][s][c][r] = 0.f; }

        const float* upb = g_Up + (w * 32 + lane) * 4;
        const float* vpb = g_Vp + (w * 32 + lane) * 4;
        float4 bu = *reinterpret_cast<const float4*>(upb);
        float4 bv = *reinterpret_cast<const float4*>(vpb);
        #pragma unroll 2
        for (int kt = 0; kt < 16; ++kt) {
            float4 bun, bvn;
            if (kt < 15) {
                bun = *reinterpret_cast<const float4*>(upb + (kt + 1) * 1024);
                bvn = *reinterpret_cast<const float4*>(vpb + (kt + 1) * 1024);
            }
            #pragma unroll
            for (int mt = 0; mt < 2; ++mt) {
                float4 a0 = *reinterpret_cast<float4*>(sVec + (0 * 2 + mt) * TSZ + kt * FS + lane * 4);
                float4 a1 = *reinterpret_cast<float4*>(sVec + (1 * 2 + mt) * TSZ + kt * FS + lane * 4);
                float4 a2 = *reinterpret_cast<float4*>(sVec + (2 * 2 + mt) * TSZ + kt * FS + lane * 4);
                mma8(accU[mt][0][0], a0, bu.x, bu.y); mma8(accU[mt][1][0], a0, bu.z, bu.w);
                mma8(accU[mt][0][1], a1, bu.x, bu.y); mma8(accU[mt][1][1], a1, bu.z, bu.w);
                mma8(accU[mt][0][2], a2, bu.x, bu.y); mma8(accU[mt][1][2], a2, bu.z, bu.w);
                mma8(accV[mt][0][0], a0, bv.x, bv.y); mma8(accV[mt][1][0], a0, bv.z, bv.w);
                mma8(accV[mt][0][1], a1, bv.x, bv.y); mma8(accV[mt][1][1], a1, bv.z, bv.w);
                mma8(accV[mt][0][2], a2, bv.x, bv.y); mma8(accV[mt][1][2], a2, bv.z, bv.w);
            }
            bu = bun; bv = bvn;
        }
        __syncthreads();   // all warps done reading sVec; safe to overwrite as sUv

        const int colbase0 = (w * 2) * 8 + 2 * tig;
        float2 ub2a = *reinterpret_cast<const float2*>(U_b + colbase0);
        float2 vb2a = *reinterpret_cast<const float2*>(V_b + colbase0);
        float2 ub2b = *reinterpret_cast<const float2*>(U_b + colbase0 + 8);
        float2 vb2b = *reinterpret_cast<const float2*>(V_b + colbase0 + 8);

        #pragma unroll
        for (int mt = 0; mt < 2; ++mt) {
            #pragma unroll
            for (int s = 0; s < 2; ++s) {
                int fr = w * 2 + s;
                int colbase = fr * 8 + 2 * tig;
                float2 ub2 = s ? ub2b : ub2a;
                float2 vb2 = s ? vb2b : vb2a;
                #pragma unroll
                for (int r = 0; r < 4; ++r) {
                    float u0 = accU[mt][s][0][r], u1 = accU[mt][s][1][r], u2 = accU[mt][s][2][r];
                    float v0 = accV[mt][s][0][r], v1 = accV[mt][s][1][r], v2 = accV[mt][s][2][r];
                    float fsu = u0 + u1 + u2;
                    float fsv = v0 + v1 + v2;
                    float inn = u0 * v0 + u1 * v1 + u2 * v2;
                    float vn2 = v0 * v0 + v1 * v1 + v2 * v2;
                    float ub = (r & 1) ? ub2.y : ub2.x;
                    float vb = (r & 1) ? vb2.y : vb2.x;
                    inner[mt][s][r] = inn + ub * fsv + vb * fsu + 3.0f * ub * vb;
                    float vn2c = vn2 + 2.0f * vb * fsv + 3.0f * vb * vb;
                    int col = colbase + (r & 1);
                    int rowl = gid + 8 * (r >> 1);
                    sVnA[mt * TSZ + aaddr(rowl, col)] = ftf32(sqrtf(fmaxf(vn2c, 0.0f)));
                }
                #pragma unroll
                for (int c = 0; c < 3; ++c)
                    *reinterpret_cast<float4*>(sUv + (c * 2 + mt) * TSZ + fr * FS + lane * 4) =
                        make_float4(accU[mt][s][c][0], accU[mt][s][c][1],
                                    accU[mt][s][c][2], accU[mt][s][c][3]);
            }
        }
    }
    __syncthreads();

    // ---------- Stage 3: h = silu([Vn | scal] @ m1 + b); B software-pipelined ----------
    {
        float acc[2][2][4];   // [mt][s][r]
        #pragma unroll
        for (int mt = 0; mt < 2; ++mt)
            #pragma unroll
            for (int s = 0; s < 2; ++s)
                #pragma unroll
                for (int r = 0; r < 4; ++r) acc[mt][s][r] = 0.f;

        const float* m1b = g_m1p + (w * 32 + lane) * 4;
        float4 b = *reinterpret_cast<const float4*>(m1b);
        #pragma unroll
        for (int kt = 0; kt < 32; ++kt) {
            float4 bn;
            if (kt < 31)
                bn = *reinterpret_cast<const float4*>(m1b + (kt + 1) * 1024);
            float* abase = (kt < 16) ? sVnA : sScal;
            int ktl = kt & 15;
            #pragma unroll
            for (int mt = 0; mt < 2; ++mt) {
                float4 a = *reinterpret_cast<float4*>(abase + mt * TSZ + ktl * FS + lane * 4);
                mma8(acc[mt][0], a, b.x, b.y);
                mma8(acc[mt][1], a, b.z, b.w);
            }
            b = bn;
        }
        #pragma unroll
        for (int mt = 0; mt < 2; ++mt) {
            #pragma unroll
            for (int s = 0; s < 2; ++s) {
                int fr = w * 2 + s;
                int colbase = fr * 8 + 2 * tig;
                float2 mb2 = *reinterpret_cast<const float2*>(m1_b + colbase);
                #pragma unroll
                for (int r = 0; r < 4; ++r) {
                    float x = acc[mt][s][r] + ((r & 1) ? mb2.y : mb2.x);
                    int col = colbase + (r & 1);
                    int rowl = gid + 8 * (r >> 1);
                    sH[mt * TSZ + aaddr(rowl, col)] = ftf32(x / (1.0f + __expf(-x)));
                }
            }
        }
    }
    __syncthreads();

    // ---------- Stage 4: mlp_out = h @ m2 + fused epilogue; B software-pipelined ----------
    {
        float acc[2][3][2][4];   // [mt][p][s][r]
        #pragma unroll
        for (int mt = 0; mt < 2; ++mt)
            #pragma unroll
            for (int p = 0; p < 3; ++p)
                #pragma unroll
                for (int s = 0; s < 2; ++s)
                    #pragma unroll
                    for (int r = 0; r < 4; ++r) acc[mt][p][s][r] = 0.f;

        float4 b[3], bn[3];
        #pragma unroll
        for (int p = 0; p < 3; ++p)
            b[p] = *reinterpret_cast<const float4*>(g_m2p + ((0 * 24 + w + p * 8) * 32 + lane) * 4);

        #pragma unroll 4
        for (int kt = 0; kt < 16; ++kt) {
            if (kt < 15) {
                #pragma unroll
                for (int p = 0; p < 3; ++p)
                    bn[p] = *reinterpret_cast<const float4*>(
                        g_m2p + (((kt + 1) * 24 + w + p * 8) * 32 + lane) * 4);
            }
            float4 a0 = *reinterpret_cast<float4*>(sH + 0 * TSZ + kt * FS + lane * 4);
            float4 a1 = *reinterpret_cast<float4*>(sH + 1 * TSZ + kt * FS + lane * 4);
            #pragma unroll
            for (int p = 0; p < 3; ++p) {
                mma8(acc[0][p][0], a0, b[p].x, b[p].y); mma8(acc[0][p][1], a0, b[p].z, b[p].w);
                mma8(acc[1][p][0], a1, b[p].x, b[p].y); mma8(acc[1][p][1], a1, b[p].z, b[p].w);
            }
            #pragma unroll
            for (int p = 0; p < 3; ++p) b[p] = bn[p];
        }

        // fused epilogue; C-fragment geometry matches inner/Uv fragments
        #pragma unroll
        for (int mt = 0; mt < 2; ++mt) {
            #pragma unroll
            for (int s = 0; s < 2; ++s) {
                int fr = w * 2 + s;
                int colb = fr * 8 + 2 * tig;
                float2 b0 = *reinterpret_cast<const float2*>(m2_b + colb);
                float2 b1 = *reinterpret_cast<const float2*>(m2_b + 128 + colb);
                float2 b2 = *reinterpret_cast<const float2*>(m2_b + 256 + colb);
                float2 ub2 = *reinterpret_cast<const float2*>(U_b + colb);

                #pragma unroll
                for (int hh = 0; hh < 2; ++hh) {
                    int row = mt * 16 + gid + 8 * hh;
                    float2 sres = *reinterpret_cast<const float2*>(nf + row * 512 + colb);
                    float2 o;
                    o.x = sres.x + (acc[mt][1][s][hh * 2 + 0] + b1.x) * inner[mt][s][hh * 2 + 0]
                        + acc[mt][2][s][hh * 2 + 0] + b2.x;
                    o.y = sres.y + (acc[mt][1][s][hh * 2 + 1] + b1.y) * inner[mt][s][hh * 2 + 1]
                        + acc[mt][2][s][hh * 2 + 1] + b2.y;
                    *reinterpret_cast<float2*>(op + row * 512 + colb) = o;
                }
                #pragma unroll
                for (int c = 0; c < 3; ++c) {
                    float4 u4 = *reinterpret_cast<float4*>(sUv + (c * 2 + mt) * TSZ + fr * FS + lane * 4);
                    const float* up = reinterpret_cast<const float*>(&u4);
                    #pragma unroll
                    for (int hh = 0; hh < 2; ++hh) {
                        int row = mt * 16 + gid + 8 * hh;
                        const float* src = nf + row * 512 + 128 + c * 128 + colb;
                        float2 v = *reinterpret_cast<const float2*>(src);
                        float2 o;
                        o.x = v.x + (acc[mt][0][s][hh * 2 + 0] + b0.x) * (up[hh * 2 + 0] + ub2.x);
                        o.y = v.y + (acc[mt][0][s][hh * 2 + 1] + b0.y) * (up[hh * 2 + 1] + ub2.y);
                        *reinterpret_cast<float2*>(op + row * 512 + 128 + c * 128 + colb) = o;
                    }
                }
            }
        }
    }
}

extern "C" void kernel_launch(void* const* d_in, const int* in_sizes, int n_in,
                              void* d_out, int out_size) {
    const float* node_feat = (const float*)d_in[0];
    const float* U_w  = (const float*)d_in[1];
    const float* U_b  = (const float*)d_in[2];
    const float* V_w  = (const float*)d_in[3];
    const float* V_b  = (const float*)d_in[4];
    const float* m1_w = (const float*)d_in[5];
    const float* m1_b = (const float*)d_in[6];
    const float* m2_w = (const float*)d_in[7];
    const float* m2_b = (const float*)d_in[8];
    float* out = (float*)d_out;

    int N = in_sizes[0] / 512;

    prep_kernel<<<(49152 + 255) / 256, 256>>>(U_w, V_w, m1_w, m2_w);

    size_t smem_bytes = SMEM_FLOATS * sizeof(float);   // 101,376 B
    cudaFuncSetAttribute(painn_kernel,
                         cudaFuncAttributeMaxDynamicSharedMemorySize,
                         (int)smem_bytes);
    painn_kernel<<<N / TM, NTHREADS, smem_bytes>>>(node_feat, U_b, V_b, m1_b, m2_b, out);
}

// round 15
// speedup vs baseline: 3.5763x; 1.0218x over previous
#include <cuda_runtime.h>
#include <cstdint>

#define NTHREADS 256
#define TM 32
#define FS  132            // floats per kt-frame (padded from 128)
#define TSZ 2112           // 16 * FS, floats per 16x128 fragment tile

// Fragment-permuted, tf32-rounded weights.
__device__ __align__(16) float g_Up[16384];
__device__ __align__(16) float g_Vp[16384];
__device__ __align__(16) float g_m1p[32768];
__device__ __align__(16) float g_m2p[49152];

__device__ __forceinline__ float ftf32(float x) {
    float y;
    asm("cvt.rna.tf32.f32 %0, %1;" : "=f"(y) : "f"(x));
    return y;
}

// B-fragment-linear address for W[k][n] (K x N), n8-pairs packed per float4.
__device__ __forceinline__ int baddr(int k, int n, int N) {
    return (((k >> 3) * (N >> 4) + (n >> 4)) * 32 + (n & 7) * 4 + (k & 3)) * 4
           + ((n >> 3) & 1) * 2 + ((k >> 2) & 1);
}

// A-fragment-linear address within a padded 16x128 tile for element (n,g).
__device__ __forceinline__ int aaddr(int n, int g) {
    return (g >> 3) * FS + ((n & 7) * 4 + (g & 3)) * 4 + ((g >> 2) & 1) * 2 + (n >> 3);
}

__global__ void prep_kernel(const float* __restrict__ Uw, const float* __restrict__ Vw,
                            const float* __restrict__ m1w, const float* __restrict__ m2w) {
    int i = blockIdx.x * blockDim.x + threadIdx.x;
    if (i < 16384) {
        int k = i >> 7, n = i & 127;
        int a = baddr(k, n, 128);
        g_Up[a] = ftf32(Uw[i]);
        g_Vp[a] = ftf32(Vw[i]);
    }
    if (i < 32768) {
        int k = i >> 7, n = i & 127;
        g_m1p[baddr(k, n, 128)] = ftf32(m1w[i]);
    }
    if (i < 49152) {
        int k = i / 384, n = i % 384;
        g_m2p[baddr(k, n, 384)] = ftf32(m2w[i]);
    }
}

__device__ __forceinline__ void mma8(float* d, float4 a, float b0, float b1) {
    asm volatile(
        "mma.sync.aligned.m16n8k8.row.col.f32.tf32.tf32.f32 "
        "{%0,%1,%2,%3}, {%4,%5,%6,%7}, {%8,%9}, {%0,%1,%2,%3};"
        : "+f"(d[0]), "+f"(d[1]), "+f"(d[2]), "+f"(d[3])
        : "r"(__float_as_uint(a.x)), "r"(__float_as_uint(a.y)),
          "r"(__float_as_uint(a.z)), "r"(__float_as_uint(a.w)),
          "r"(__float_as_uint(b0)), "r"(__float_as_uint(b1)));
}

// smem float offsets (padded tiles of TSZ floats)
#define SVEC   0                 // 6 tiles (c*2+mt); aliased as sUv after stage 1
#define SSCAL  (6 * TSZ)         // 2 tiles (mt)
#define SVNA   (8 * TSZ)         // 2 tiles (mt)
#define SH     (10 * TSZ)        // 2 tiles (mt)
#define SMEM_FLOATS (12 * TSZ)   // 25344 floats = 101376 B

__global__ __launch_bounds__(NTHREADS, 2)
void painn_kernel(const float* __restrict__ node_feat,
                  const float* __restrict__ U_b,
                  const float* __restrict__ V_b,
                  const float* __restrict__ m1_b,
                  const float* __restrict__ m2_b,
                  float* __restrict__ out) {
    extern __shared__ float smem[];
    float* sVec  = smem + SVEC;
    float* sUv   = smem + SVEC;         // alias, valid after stage-1 barrier
    float* sScal = smem + SSCAL;
    float* sVnA  = smem + SVNA;
    float* sH    = smem + SH;

    const int tid  = threadIdx.x;
    const int w    = tid >> 5;          // 0..7
    const int lane = tid & 31;
    const int tig  = lane & 3;
    const int gid  = lane >> 2;
    const size_t base = (size_t)blockIdx.x * (TM * 512);
    const float* nf = node_feat + base;
    float* op = out + base;

    // ---------- Stage 0: stage 32-node tile, A-fragment layout, tf32 RNA ----------
    #pragma unroll
    for (int it = 0; it < TM * 128 / NTHREADS; ++it) {
        int q  = tid + it * NTHREADS;
        int n  = q >> 7;                // 0..31
        int f0 = (q & 127) * 4;
        int mt = n >> 4;
        int nl = n & 15;
        float4 v = *reinterpret_cast<const float4*>(nf + n * 512 + f0);
        v.x = ftf32(v.x); v.y = ftf32(v.y); v.z = ftf32(v.z); v.w = ftf32(v.w);
        float* dstb;
        int g;
        if (f0 < 128) { dstb = sScal + mt * TSZ; g = f0; }
        else {
            int c = (f0 - 128) >> 7;
            g = (f0 - 128) & 127;
            dstb = sVec + (c * 2 + mt) * TSZ;
        }
        int r = ((g >> 2) & 1) * 2 + (nl >> 3);
        int b0 = (g >> 3) * FS + (nl & 7) * 16 + r;   // g&3 == 0
        dstb[b0 + 0]  = v.x;
        dstb[b0 + 4]  = v.y;
        dstb[b0 + 8]  = v.z;
        dstb[b0 + 12] = v.w;
    }
    __syncthreads();

    float inner[2][2][4];   // [mt][s][r], persists to epilogue

    // ---------- Stage 1: Uv/Vv GEMMs; B reused across 2 m-tiles, B prefetched ----------
    {
        float accU[2][2][3][4], accV[2][2][3][4];   // [mt][s][c][r]
        #pragma unroll
        for (int mt = 0; mt < 2; ++mt)
            #pragma unroll
            for (int s = 0; s < 2; ++s)
                #pragma unroll
                for (int c = 0; c < 3; ++c)
                    #pragma unroll
                    for (int r = 0; r < 4; ++r) { accU[mt][s][c][r] = 0.f; accV[mt][s][c][r] = 0.f; }

        const float* upb = g_Up + (w * 32 + lane) * 4;
        const float* vpb = g_Vp + (w * 32 + lane) * 4;
        float4 bu = *reinterpret_cast<const float4*>(upb);
        float4 bv = *reinterpret_cast<const float4*>(vpb);
        #pragma unroll 2
        for (int kt = 0; kt < 16; ++kt) {
            float4 bun, bvn;
            if (kt < 15) {
                bun = *reinterpret_cast<const float4*>(upb + (kt + 1) * 1024);
                bvn = *reinterpret_cast<const float4*>(vpb + (kt + 1) * 1024);
            }
            #pragma unroll
            for (int mt = 0; mt < 2; ++mt) {
                float4 a0 = *reinterpret_cast<float4*>(sVec + (0 * 2 + mt) * TSZ + kt * FS + lane * 4);
                float4 a1 = *reinterpret_cast<float4*>(sVec + (1 * 2 + mt) * TSZ + kt * FS + lane * 4);
                float4 a2 = *reinterpret_cast<float4*>(sVec + (2 * 2 + mt) * TSZ + kt * FS + lane * 4);
                mma8(accU[mt][0][0], a0, bu.x, bu.y); mma8(accU[mt][1][0], a0, bu.z, bu.w);
                mma8(accU[mt][0][1], a1, bu.x, bu.y); mma8(accU[mt][1][1], a1, bu.z, bu.w);
                mma8(accU[mt][0][2], a2, bu.x, bu.y); mma8(accU[mt][1][2], a2, bu.z, bu.w);
                mma8(accV[mt][0][0], a0, bv.x, bv.y); mma8(accV[mt][1][0], a0, bv.z, bv.w);
                mma8(accV[mt][0][1], a1, bv.x, bv.y); mma8(accV[mt][1][1], a1, bv.z, bv.w);
                mma8(accV[mt][0][2], a2, bv.x, bv.y); mma8(accV[mt][1][2], a2, bv.z, bv.w);
            }
            bu = bun; bv = bvn;
        }
        __syncthreads();   // all warps done reading sVec; safe to overwrite as sUv

        const int colbase0 = (w * 2) * 8 + 2 * tig;
        float2 ub2a = *reinterpret_cast<const float2*>(U_b + colbase0);
        float2 vb2a = *reinterpret_cast<const float2*>(V_b + colbase0);
        float2 ub2b = *reinterpret_cast<const float2*>(U_b + colbase0 + 8);
        float2 vb2b = *reinterpret_cast<const float2*>(V_b + colbase0 + 8);

        #pragma unroll
        for (int mt = 0; mt < 2; ++mt) {
            #pragma unroll
            for (int s = 0; s < 2; ++s) {
                int fr = w * 2 + s;
                int colbase = fr * 8 + 2 * tig;
                float2 ub2 = s ? ub2b : ub2a;
                float2 vb2 = s ? vb2b : vb2a;
                #pragma unroll
                for (int r = 0; r < 4; ++r) {
                    float u0 = accU[mt][s][0][r], u1 = accU[mt][s][1][r], u2 = accU[mt][s][2][r];
                    float v0 = accV[mt][s][0][r], v1 = accV[mt][s][1][r], v2 = accV[mt][s][2][r];
                    float fsu = u0 + u1 + u2;
                    float fsv = v0 + v1 + v2;
                    float inn = u0 * v0 + u1 * v1 + u2 * v2;
                    float vn2 = v0 * v0 + v1 * v1 + v2 * v2;
                    float ub = (r & 1) ? ub2.y : ub2.x;
                    float vb = (r & 1) ? vb2.y : vb2.x;
                    inner[mt][s][r] = inn + ub * fsv + vb * fsu + 3.0f * ub * vb;
                    float vn2c = vn2 + 2.0f * vb * fsv + 3.0f * vb * vb;
                    int col = colbase + (r & 1);
                    int rowl = gid + 8 * (r >> 1);
                    sVnA[mt * TSZ + aaddr(rowl, col)] = ftf32(sqrtf(fmaxf(vn2c, 0.0f)));
                }
                #pragma unroll
                for (int c = 0; c < 3; ++c)
                    *reinterpret_cast<float4*>(sUv + (c * 2 + mt) * TSZ + fr * FS + lane * 4) =
                        make_float4(accU[mt][s][c][0], accU[mt][s][c][1],
                                    accU[mt][s][c][2], accU[mt][s][c][3]);
            }
        }
    }
    __syncthreads();

    // ---------- Stage 3: h = silu([Vn | scal] @ m1 + b); B prefetch distance 4 ----------
    {
        float acc[2][2][4];   // [mt][s][r]
        #pragma unroll
        for (int mt = 0; mt < 2; ++mt)
            #pragma unroll
            for (int s = 0; s < 2; ++s)
                #pragma unroll
                for (int r = 0; r < 4; ++r) acc[mt][s][r] = 0.f;

        const float* m1b = g_m1p + (w * 32 + lane) * 4;
        float4 bq[4];
        #pragma unroll
        for (int i = 0; i < 4; ++i)
            bq[i] = *reinterpret_cast<const float4*>(m1b + i * 1024);

        #pragma unroll
        for (int kt = 0; kt < 32; ++kt) {
            float4 b = bq[kt & 3];
            if (kt < 28)
                bq[kt & 3] = *reinterpret_cast<const float4*>(m1b + (kt + 4) * 1024);
            float* abase = (kt < 16) ? sVnA : sScal;
            int ktl = kt & 15;
            #pragma unroll
            for (int mt = 0; mt < 2; ++mt) {
                float4 a = *reinterpret_cast<float4*>(abase + mt * TSZ + ktl * FS + lane * 4);
                mma8(acc[mt][0], a, b.x, b.y);
                mma8(acc[mt][1], a, b.z, b.w);
            }
        }
        #pragma unroll
        for (int mt = 0; mt < 2; ++mt) {
            #pragma unroll
            for (int s = 0; s < 2; ++s) {
                int fr = w * 2 + s;
                int colbase = fr * 8 + 2 * tig;
                float2 mb2 = *reinterpret_cast<const float2*>(m1_b + colbase);
                #pragma unroll
                for (int r = 0; r < 4; ++r) {
                    float x = acc[mt][s][r] + ((r & 1) ? mb2.y : mb2.x);
                    int col = colbase + (r & 1);
                    int rowl = gid + 8 * (r >> 1);
                    sH[mt * TSZ + aaddr(rowl, col)] = ftf32(x / (1.0f + __expf(-x)));
                }
            }
        }
    }
    __syncthreads();

    // ---------- Stage 4: mlp_out = h @ m2 + fused epilogue; B prefetch distance 2 ----------
    {
        float acc[2][3][2][4];   // [mt][p][s][r]
        #pragma unroll
        for (int mt = 0; mt < 2; ++mt)
            #pragma unroll
            for (int p = 0; p < 3; ++p)
                #pragma unroll
                for (int s = 0; s < 2; ++s)
                    #pragma unroll
                    for (int r = 0; r < 4; ++r) acc[mt][p][s][r] = 0.f;

        float4 b[2][3];
        #pragma unroll
        for (int d = 0; d < 2; ++d)
            #pragma unroll
            for (int p = 0; p < 3; ++p)
                b[d][p] = *reinterpret_cast<const float4*>(
                    g_m2p + ((d * 24 + w + p * 8) * 32 + lane) * 4);

        #pragma unroll 4
        for (int kt = 0; kt < 16; ++kt) {
            float4 bcur[3];
            #pragma unroll
            for (int p = 0; p < 3; ++p) bcur[p] = b[kt & 1][p];
            if (kt < 14) {
                #pragma unroll
                for (int p = 0; p < 3; ++p)
                    b[kt & 1][p] = *reinterpret_cast<const float4*>(
                        g_m2p + (((kt + 2) * 24 + w + p * 8) * 32 + lane) * 4);
            }
            float4 a0 = *reinterpret_cast<float4*>(sH + 0 * TSZ + kt * FS + lane * 4);
            float4 a1 = *reinterpret_cast<float4*>(sH + 1 * TSZ + kt * FS + lane * 4);
            #pragma unroll
            for (int p = 0; p < 3; ++p) {
                mma8(acc[0][p][0], a0, bcur[p].x, bcur[p].y); mma8(acc[0][p][1], a0, bcur[p].z, bcur[p].w);
                mma8(acc[1][p][0], a1, bcur[p].x, bcur[p].y); mma8(acc[1][p][1], a1, bcur[p].z, bcur[p].w);
            }
        }

        // fused epilogue; C-fragment geometry matches inner/Uv fragments
        #pragma unroll
        for (int mt = 0; mt < 2; ++mt) {
            #pragma unroll
            for (int s = 0; s < 2; ++s) {
                int fr = w * 2 + s;
                int colb = fr * 8 + 2 * tig;
                float2 b0 = *reinterpret_cast<const float2*>(m2_b + colb);
                float2 b1 = *reinterpret_cast<const float2*>(m2_b + 128 + colb);
                float2 b2 = *reinterpret_cast<const float2*>(m2_b + 256 + colb);
                float2 ub2 = *reinterpret_cast<const float2*>(U_b + colb);

                #pragma unroll
                for (int hh = 0; hh < 2; ++hh) {
                    int row = mt * 16 + gid + 8 * hh;
                    float2 sres = *reinterpret_cast<const float2*>(nf + row * 512 + colb);
                    float2 o;
                    o.x = sres.x + (acc[mt][1][s][hh * 2 + 0] + b1.x) * inner[mt][s][hh * 2 + 0]
                        + acc[mt][2][s][hh * 2 + 0] + b2.x;
                    o.y = sres.y + (acc[mt][1][s][hh * 2 + 1] + b1.y) * inner[mt][s][hh * 2 + 1]
                        + acc[mt][2][s][hh * 2 + 1] + b2.y;
                    *reinterpret_cast<float2*>(op + row * 512 + colb) = o;
                }
                #pragma unroll
                for (int c = 0; c < 3; ++c) {
                    float4 u4 = *reinterpret_cast<float4*>(sUv + (c * 2 + mt) * TSZ + fr * FS + lane * 4);
                    const float* up = reinterpret_cast<const float*>(&u4);
                    #pragma unroll
                    for (int hh = 0; hh < 2; ++hh) {
                        int row = mt * 16 + gid + 8 * hh;
                        const float* src = nf + row * 512 + 128 + c * 128 + colb;
                        float2 v = *reinterpret_cast<const float2*>(src);
                        float2 o;
                        o.x = v.x + (acc[mt][0][s][hh * 2 + 0] + b0.x) * (up[hh * 2 + 0] + ub2.x);
                        o.y = v.y + (acc[mt][0][s][hh * 2 + 1] + b0.y) * (up[hh * 2 + 1] + ub2.y);
                        *reinterpret_cast<float2*>(op + row * 512 + 128 + c * 128 + colb) = o;
                    }
                }
            }
        }
    }
}

extern "C" void kernel_launch(void* const* d_in, const int* in_sizes, int n_in,
                              void* d_out, int out_size) {
    const float* node_feat = (const float*)d_in[0];
    const float* U_w  = (const float*)d_in[1];
    const float* U_b  = (const float*)d_in[2];
    const float* V_w  = (const float*)d_in[3];
    const float* V_b  = (const float*)d_in[4];
    const float* m1_w = (const float*)d_in[5];
    const float* m1_b = (const float*)d_in[6];
    const float* m2_w = (const float*)d_in[7];
    const float* m2_b = (const float*)d_in[8];
    float* out = (float*)d_out;

    int N = in_sizes[0] / 512;

    prep_kernel<<<(49152 + 255) / 256, 256>>>(U_w, V_w, m1_w, m2_w);

    size_t smem_bytes = SMEM_FLOATS * sizeof(float);   // 101,376 B
    cudaFuncSetAttribute(painn_kernel,
                         cudaFuncAttributeMaxDynamicSharedMemorySize,
                         (int)smem_bytes);
    painn_kernel<<<N / TM, NTHREADS, smem_bytes>>>(node_feat, U_b, V_b, m1_b, m2_b, out);
}

// round 17
// speedup vs baseline: 3.7840x; 1.0581x over previous
#include <cuda_runtime.h>
#include <cstdint>

#define NTHREADS 256
#define TM 32
#define FS  132            // floats per kt-frame (padded from 128)
#define TSZ 2112           // 16 * FS, floats per 16x128 fragment tile
#define OBUF_ROW 132       // output-buffer row stride (floats)
#define OBUF_PART (32 * OBUF_ROW)

// Fragment-permuted, tf32-rounded weights.
__device__ __align__(16) float g_Up[16384];
__device__ __align__(16) float g_Vp[16384];
__device__ __align__(16) float g_m1p[32768];
__device__ __align__(16) float g_m2p[49152];

__device__ __forceinline__ float ftf32(float x) {
    float y;
    asm("cvt.rna.tf32.f32 %0, %1;" : "=f"(y) : "f"(x));
    return y;
}

__device__ __forceinline__ int baddr(int k, int n, int N) {
    return (((k >> 3) * (N >> 4) + (n >> 4)) * 32 + (n & 7) * 4 + (k & 3)) * 4
           + ((n >> 3) & 1) * 2 + ((k >> 2) & 1);
}

__device__ __forceinline__ int aaddr(int n, int g) {
    return (g >> 3) * FS + ((n & 7) * 4 + (g & 3)) * 4 + ((g >> 2) & 1) * 2 + (n >> 3);
}

__global__ void prep_kernel(const float* __restrict__ Uw, const float* __restrict__ Vw,
                            const float* __restrict__ m1w, const float* __restrict__ m2w) {
    int i = blockIdx.x * blockDim.x + threadIdx.x;
    if (i < 16384) {
        int k = i >> 7, n = i & 127;
        int a = baddr(k, n, 128);
        g_Up[a] = ftf32(Uw[i]);
        g_Vp[a] = ftf32(Vw[i]);
    }
    if (i < 32768) {
        int k = i >> 7, n = i & 127;
        g_m1p[baddr(k, n, 128)] = ftf32(m1w[i]);
    }
    if (i < 49152) {
        int k = i / 384, n = i % 384;
        g_m2p[baddr(k, n, 384)] = ftf32(m2w[i]);
    }
}

__device__ __forceinline__ void mma8(float* d, float4 a, float b0, float b1) {
    asm volatile(
        "mma.sync.aligned.m16n8k8.row.col.f32.tf32.tf32.f32 "
        "{%0,%1,%2,%3}, {%4,%5,%6,%7}, {%8,%9}, {%0,%1,%2,%3};"
        : "+f"(d[0]), "+f"(d[1]), "+f"(d[2]), "+f"(d[3])
        : "r"(__float_as_uint(a.x)), "r"(__float_as_uint(a.y)),
          "r"(__float_as_uint(a.z)), "r"(__float_as_uint(a.w)),
          "r"(__float_as_uint(b0)), "r"(__float_as_uint(b1)));
}

// smem float offsets (padded tiles of TSZ floats)
#define SVEC   0                 // 6 tiles (c*2+mt); aliased as sUv after stage 1
#define SSCAL  (6 * TSZ)         // 2 tiles (mt); overlaid by output buffer in epilogue
#define SVNA   (8 * TSZ)         // 2 tiles (mt); overlaid by output buffer in epilogue
#define SH     (10 * TSZ)        // 2 tiles (mt)
#define SMEM_FLOATS (12 * TSZ)   // 25344 floats = 101376 B

__global__ __launch_bounds__(NTHREADS, 2)
void painn_kernel(const float* __restrict__ node_feat,
                  const float* __restrict__ U_b,
                  const float* __restrict__ V_b,
                  const float* __restrict__ m1_b,
                  const float* __restrict__ m2_b,
                  float* __restrict__ out) {
    extern __shared__ float smem[];
    float* sVec  = smem + SVEC;
    float* sUv   = smem + SVEC;         // alias, valid after stage-1 barrier
    float* sScal = smem + SSCAL;
    float* sVnA  = smem + SVNA;
    float* sH    = smem + SH;
    float* sObuf = smem + SSCAL;        // 2 parts x 32 x OBUF_ROW (epilogue only)

    const int tid  = threadIdx.x;
    const int w    = tid >> 5;          // 0..7
    const int lane = tid & 31;
    const int tig  = lane & 3;
    const int gid  = lane >> 2;
    const size_t base = (size_t)blockIdx.x * (TM * 512);
    const float* nf = node_feat + base;
    float* op = out + base;

    // ---------- Stage 0: stage 32-node tile, A-fragment layout, tf32 RNA ----------
    #pragma unroll
    for (int it = 0; it < TM * 128 / NTHREADS; ++it) {
        int q  = tid + it * NTHREADS;
        int n  = q >> 7;                // 0..31
        int f0 = (q & 127) * 4;
        int mt = n >> 4;
        int nl = n & 15;
        float4 v = *reinterpret_cast<const float4*>(nf + n * 512 + f0);
        v.x = ftf32(v.x); v.y = ftf32(v.y); v.z = ftf32(v.z); v.w = ftf32(v.w);
        float* dstb;
        int g;
        if (f0 < 128) { dstb = sScal + mt * TSZ; g = f0; }
        else {
            int c = (f0 - 128) >> 7;
            g = (f0 - 128) & 127;
            dstb = sVec + (c * 2 + mt) * TSZ;
        }
        int r = ((g >> 2) & 1) * 2 + (nl >> 3);
        int b0 = (g >> 3) * FS + (nl & 7) * 16 + r;   // g&3 == 0
        dstb[b0 + 0]  = v.x;
        dstb[b0 + 4]  = v.y;
        dstb[b0 + 8]  = v.z;
        dstb[b0 + 12] = v.w;
    }
    __syncthreads();

    float inner[2][2][4];   // [mt][s][r], persists to epilogue

    // ---------- Stage 1: Uv/Vv GEMMs; B reused across 2 m-tiles, B prefetched ----------
    {
        float accU[2][2][3][4], accV[2][2][3][4];   // [mt][s][c][r]
        #pragma unroll
        for (int mt = 0; mt < 2; ++mt)
            #pragma unroll
            for (int s = 0; s < 2; ++s)
                #pragma unroll
                for (int c = 0; c < 3; ++c)
                    #pragma unroll
                    for (int r = 0; r < 4; ++r) { accU[mt][s][c][r] = 0.f; accV[mt][s][c][r] = 0.f; }

        const float* upb = g_Up + (w * 32 + lane) * 4;
        const float* vpb = g_Vp + (w * 32 + lane) * 4;
        float4 bu = *reinterpret_cast<const float4*>(upb);
        float4 bv = *reinterpret_cast<const float4*>(vpb);
        #pragma unroll 2
        for (int kt = 0; kt < 16; ++kt) {
            float4 bun, bvn;
            if (kt < 15) {
                bun = *reinterpret_cast<const float4*>(upb + (kt + 1) * 1024);
                bvn = *reinterpret_cast<const float4*>(vpb + (kt + 1) * 1024);
            }
            #pragma unroll
            for (int mt = 0; mt < 2; ++mt) {
                float4 a0 = *reinterpret_cast<float4*>(sVec + (0 * 2 + mt) * TSZ + kt * FS + lane * 4);
                float4 a1 = *reinterpret_cast<float4*>(sVec + (1 * 2 + mt) * TSZ + kt * FS + lane * 4);
                float4 a2 = *reinterpret_cast<float4*>(sVec + (2 * 2 + mt) * TSZ + kt * FS + lane * 4);
                mma8(accU[mt][0][0], a0, bu.x, bu.y); mma8(accU[mt][1][0], a0, bu.z, bu.w);
                mma8(accU[mt][0][1], a1, bu.x, bu.y); mma8(accU[mt][1][1], a1, bu.z, bu.w);
                mma8(accU[mt][0][2], a2, bu.x, bu.y); mma8(accU[mt][1][2], a2, bu.z, bu.w);
                mma8(accV[mt][0][0], a0, bv.x, bv.y); mma8(accV[mt][1][0], a0, bv.z, bv.w);
                mma8(accV[mt][0][1], a1, bv.x, bv.y); mma8(accV[mt][1][1], a1, bv.z, bv.w);
                mma8(accV[mt][0][2], a2, bv.x, bv.y); mma8(accV[mt][1][2], a2, bv.z, bv.w);
            }
            bu = bun; bv = bvn;
        }
        __syncthreads();   // all warps done reading sVec; safe to overwrite as sUv

        const int colbase0 = (w * 2) * 8 + 2 * tig;
        float2 ub2a = *reinterpret_cast<const float2*>(U_b + colbase0);
        float2 vb2a = *reinterpret_cast<const float2*>(V_b + colbase0);
        float2 ub2b = *reinterpret_cast<const float2*>(U_b + colbase0 + 8);
        float2 vb2b = *reinterpret_cast<const float2*>(V_b + colbase0 + 8);

        #pragma unroll
        for (int mt = 0; mt < 2; ++mt) {
            #pragma unroll
            for (int s = 0; s < 2; ++s) {
                int fr = w * 2 + s;
                int colbase = fr * 8 + 2 * tig;
                float2 ub2 = s ? ub2b : ub2a;
                float2 vb2 = s ? vb2b : vb2a;
                #pragma unroll
                for (int r = 0; r < 4; ++r) {
                    float u0 = accU[mt][s][0][r], u1 = accU[mt][s][1][r], u2 = accU[mt][s][2][r];
                    float v0 = accV[mt][s][0][r], v1 = accV[mt][s][1][r], v2 = accV[mt][s][2][r];
                    float fsu = u0 + u1 + u2;
                    float fsv = v0 + v1 + v2;
                    float inn = u0 * v0 + u1 * v1 + u2 * v2;
                    float vn2 = v0 * v0 + v1 * v1 + v2 * v2;
                    float ub = (r & 1) ? ub2.y : ub2.x;
                    float vb = (r & 1) ? vb2.y : vb2.x;
                    inner[mt][s][r] = inn + ub * fsv + vb * fsu + 3.0f * ub * vb;
                    float vn2c = vn2 + 2.0f * vb * fsv + 3.0f * vb * vb;
                    int col = colbase + (r & 1);
                    int rowl = gid + 8 * (r >> 1);
                    sVnA[mt * TSZ + aaddr(rowl, col)] = ftf32(sqrtf(fmaxf(vn2c, 0.0f)));
                }
                #pragma unroll
                for (int c = 0; c < 3; ++c)
                    *reinterpret_cast<float4*>(sUv + (c * 2 + mt) * TSZ + fr * FS + lane * 4) =
                        make_float4(accU[mt][s][c][0], accU[mt][s][c][1],
                                    accU[mt][s][c][2], accU[mt][s][c][3]);
            }
        }
    }
    __syncthreads();

    // ---------- Stage 3: h = silu([Vn | scal] @ m1 + b); B dist-4, A dist-2 ----------
    {
        float acc[2][2][4];   // [mt][s][r]
        #pragma unroll
        for (int mt = 0; mt < 2; ++mt)
            #pragma unroll
            for (int s = 0; s < 2; ++s)
                #pragma unroll
                for (int r = 0; r < 4; ++r) acc[mt][s][r] = 0.f;

        const float* m1b = g_m1p + (w * 32 + lane) * 4;
        float4 bq[4];
        #pragma unroll
        for (int i = 0; i < 4; ++i)
            bq[i] = *reinterpret_cast<const float4*>(m1b + i * 1024);

        float4 aq[2][2];   // [parity][mt], A prefetch distance 2
        #pragma unroll
        for (int d = 0; d < 2; ++d)
            #pragma unroll
            for (int mt = 0; mt < 2; ++mt)
                aq[d][mt] = *reinterpret_cast<float4*>(sVnA + mt * TSZ + d * FS + lane * 4);

        #pragma unroll
        for (int kt = 0; kt < 32; ++kt) {
            float4 b = bq[kt & 3];
            if (kt < 28)
                bq[kt & 3] = *reinterpret_cast<const float4*>(m1b + (kt + 4) * 1024);
            float4 a0 = aq[kt & 1][0];
            float4 a1 = aq[kt & 1][1];
            if (kt < 30) {
                float* ab = (kt + 2 < 16) ? sVnA : sScal;
                int ktl = (kt + 2) & 15;
                aq[kt & 1][0] = *reinterpret_cast<float4*>(ab + 0 * TSZ + ktl * FS + lane * 4);
                aq[kt & 1][1] = *reinterpret_cast<float4*>(ab + 1 * TSZ + ktl * FS + lane * 4);
            }
            mma8(acc[0][0], a0, b.x, b.y);
            mma8(acc[0][1], a0, b.z, b.w);
            mma8(acc[1][0], a1, b.x, b.y);
            mma8(acc[1][1], a1, b.z, b.w);
        }
        #pragma unroll
        for (int mt = 0; mt < 2; ++mt) {
            #pragma unroll
            for (int s = 0; s < 2; ++s) {
                int fr = w * 2 + s;
                int colbase = fr * 8 + 2 * tig;
                float2 mb2 = *reinterpret_cast<const float2*>(m1_b + colbase);
                #pragma unroll
                for (int r = 0; r < 4; ++r) {
                    float x = acc[mt][s][r] + ((r & 1) ? mb2.y : mb2.x);
                    int col = colbase + (r & 1);
                    int rowl = gid + 8 * (r >> 1);
                    sH[mt * TSZ + aaddr(rowl, col)] = ftf32(x / (1.0f + __expf(-x)));
                }
            }
        }
    }
    __syncthreads();

    // ---------- Stage 4: mlp_out = h @ m2 (B dist-2, A dist-1) + coalesced epilogue ----------
    {
        float acc[2][3][2][4];   // [mt][p][s][r]
        #pragma unroll
        for (int mt = 0; mt < 2; ++mt)
            #pragma unroll
            for (int p = 0; p < 3; ++p)
                #pragma unroll
                for (int s = 0; s < 2; ++s)
                    #pragma unroll
                    for (int r = 0; r < 4; ++r) acc[mt][p][s][r] = 0.f;

        float4 b[2][3];
        #pragma unroll
        for (int d = 0; d < 2; ++d)
            #pragma unroll
            for (int p = 0; p < 3; ++p)
                b[d][p] = *reinterpret_cast<const float4*>(
                    g_m2p + ((d * 24 + w + p * 8) * 32 + lane) * 4);

        float4 a0n = *reinterpret_cast<float4*>(sH + 0 * TSZ + lane * 4);
        float4 a1n = *reinterpret_cast<float4*>(sH + 1 * TSZ + lane * 4);

        #pragma unroll 4
        for (int kt = 0; kt < 16; ++kt) {
            float4 bcur[3];
            #pragma unroll
            for (int p = 0; p < 3; ++p) bcur[p] = b[kt & 1][p];
            if (kt < 14) {
                #pragma unroll
                for (int p = 0; p < 3; ++p)
                    b[kt & 1][p] = *reinterpret_cast<const float4*>(
                        g_m2p + (((kt + 2) * 24 + w + p * 8) * 32 + lane) * 4);
            }
            float4 a0 = a0n, a1 = a1n;
            if (kt < 15) {
                a0n = *reinterpret_cast<float4*>(sH + 0 * TSZ + (kt + 1) * FS + lane * 4);
                a1n = *reinterpret_cast<float4*>(sH + 1 * TSZ + (kt + 1) * FS + lane * 4);
            }
            #pragma unroll
            for (int p = 0; p < 3; ++p) {
                mma8(acc[0][p][0], a0, bcur[p].x, bcur[p].y); mma8(acc[0][p][1], a0, bcur[p].z, bcur[p].w);
                mma8(acc[1][p][0], a1, bcur[p].x, bcur[p].y); mma8(acc[1][p][1], a1, bcur[p].z, bcur[p].w);
            }
        }

        // ----- Pass A math: scalar (part 0) + vec c=0 (part 1), no residual -----
        // sObuf overlays sScal/sVnA (both dead). No barrier needed: stage-4 loop
        // reads only sH + weights, and the stage-3 barrier ordered sScal/sVnA reads.
        #pragma unroll
        for (int s = 0; s < 2; ++s) {
            int fr = w * 2 + s;
            int colb = fr * 8 + 2 * tig;
            float2 b0 = *reinterpret_cast<const float2*>(m2_b + colb);
            float2 b1 = *reinterpret_cast<const float2*>(m2_b + 128 + colb);
            float2 b2 = *reinterpret_cast<const float2*>(m2_b + 256 + colb);
            float2 ub2 = *reinterpret_cast<const float2*>(U_b + colb);
            #pragma unroll
            for (int mt = 0; mt < 2; ++mt) {
                float4 u4 = *reinterpret_cast<float4*>(sUv + (0 * 2 + mt) * TSZ + fr * FS + lane * 4);
                const float* up = reinterpret_cast<const float*>(&u4);
                #pragma unroll
                for (int hh = 0; hh < 2; ++hh) {
                    int n = mt * 16 + gid + 8 * hh;
                    float2 o;
                    o.x = (acc[mt][1][s][hh * 2 + 0] + b1.x) * inner[mt][s][hh * 2 + 0]
                        + acc[mt][2][s][hh * 2 + 0] + b2.x;
                    o.y = (acc[mt][1][s][hh * 2 + 1] + b1.y) * inner[mt][s][hh * 2 + 1]
                        + acc[mt][2][s][hh * 2 + 1] + b2.y;
                    *reinterpret_cast<float2*>(sObuf + n * OBUF_ROW + colb) = o;
                    float2 ov;
                    ov.x = (acc[mt][0][s][hh * 2 + 0] + b0.x) * (up[hh * 2 + 0] + ub2.x);
                    ov.y = (acc[mt][0][s][hh * 2 + 1] + b0.y) * (up[hh * 2 + 1] + ub2.y);
                    *reinterpret_cast<float2*>(sObuf + OBUF_PART + n * OBUF_ROW + colb) = ov;
                }
            }
        }
        __syncthreads();

        // ----- Flush A: parts -> global cols {0,128}, fully coalesced -----
        #pragma unroll
        for (int it = 0; it < 8; ++it) {
            int q  = tid + it * NTHREADS;
            int pp = q >> 10;
            int n  = (q >> 5) & 31;
            int g4 = (q & 31) * 4;
            float4 d = *reinterpret_cast<float4*>(sObuf + pp * OBUF_PART + n * OBUF_ROW + g4);
            int gcol = pp * 128 + g4;
            float4 r = *reinterpret_cast<const float4*>(nf + n * 512 + gcol);
            r.x += d.x; r.y += d.y; r.z += d.z; r.w += d.w;
            *reinterpret_cast<float4*>(op + n * 512 + gcol) = r;
        }
        __syncthreads();

        // ----- Pass B math: vec c=1 (part 0), c=2 (part 1) -----
        #pragma unroll
        for (int s = 0; s < 2; ++s) {
            int fr = w * 2 + s;
            int colb = fr * 8 + 2 * tig;
            float2 b0 = *reinterpret_cast<const float2*>(m2_b + colb);
            float2 ub2 = *reinterpret_cast<const float2*>(U_b + colb);
            #pragma unroll
            for (int c = 1; c < 3; ++c) {
                #pragma unroll
                for (int mt = 0; mt < 2; ++mt) {
                    float4 u4 = *reinterpret_cast<float4*>(sUv + (c * 2 + mt) * TSZ + fr * FS + lane * 4);
                    const float* up = reinterpret_cast<const float*>(&u4);
                    #pragma unroll
                    for (int hh = 0; hh < 2; ++hh) {
                        int n = mt * 16 + gid + 8 * hh;
                        float2 ov;
                        ov.x = (acc[mt][0][s][hh * 2 + 0] + b0.x) * (up[hh * 2 + 0] + ub2.x);
                        ov.y = (acc[mt][0][s][hh * 2 + 1] + b0.y) * (up[hh * 2 + 1] + ub2.y);
                        *reinterpret_cast<float2*>(sObuf + (c - 1) * OBUF_PART + n * OBUF_ROW + colb) = ov;
                    }
                }
            }
        }
        __syncthreads();

        // ----- Flush B: parts -> global cols {256,384} -----
        #pragma unroll
        for (int it = 0; it < 8; ++it) {
            int q  = tid + it * NTHREADS;
            int pp = q >> 10;
            int n  = (q >> 5) & 31;
            int g4 = (q & 31) * 4;
            float4 d = *reinterpret_cast<float4*>(sObuf + pp * OBUF_PART + n * OBUF_ROW + g4);
            int gcol = 256 + pp * 128 + g4;
            float4 r = *reinterpret_cast<const float4*>(nf + n * 512 + gcol);
            r.x += d.x; r.y += d.y; r.z += d.z; r.w += d.w;
            *reinterpret_cast<float4*>(op + n * 512 + gcol) = r;
        }
    }
}

extern "C" void kernel_launch(void* const* d_in, const int* in_sizes, int n_in,
                              void* d_out, int out_size) {
    const float* node_feat = (const float*)d_in[0];
    const float* U_w  = (const float*)d_in[1];
    const float* U_b  = (const float*)d_in[2];
    const float* V_w  = (const float*)d_in[3];
    const float* V_b  = (const float*)d_in[4];
    const float* m1_w = (const float*)d_in[5];
    const float* m1_b = (const float*)d_in[6];
    const float* m2_w = (const float*)d_in[7];
    const float* m2_b = (const float*)d_in[8];
    float* out = (float*)d_out;

    int N = in_sizes[0] / 512;

    prep_kernel<<<(49152 + 255) / 256, 256>>>(U_w, V_w, m1_w, m2_w);

    size_t smem_bytes = SMEM_FLOATS * sizeof(float);   // 101,376 B
    cudaFuncSetAttribute(painn_kernel,
                         cudaFuncAttributeMaxDynamicSharedMemorySize,
                         (int)smem_bytes);
    painn_kernel<<<N / TM, NTHREADS, smem_bytes>>>(node_feat, U_b, V_b, m1_b, m2_b, out);
}